// round 4
// baseline (speedup 1.0000x reference)
#include <cuda_runtime.h>
#include <cuda_bf16.h>
#include <math.h>
#include <stdint.h>

#define HIDDEN    2048
#define NUM_HEADS 16
#define HEAD_DIM  128
#define WINDOW    256
#define BATCH     2
#define SEQ       2048
#define M_ROWS    (BATCH * SEQ)        // 4096

// -------- scratch (static device buffers; no allocation allowed) --------
__device__ float g_Q[BATCH * NUM_HEADS * SEQ * HEAD_DIM];
__device__ float g_K[BATCH * NUM_HEADS * SEQ * HEAD_DIM];
__device__ float g_V[BATCH * NUM_HEADS * SEQ * HEAD_DIM];
__device__ float g_AO[BATCH * SEQ * HIDDEN];    // x_perm first, then attention output
__device__ float g_AO2[BATCH * SEQ * HIDDEN];   // permuted attention output
__device__ float g_WT[HIDDEN * HIDDEN];         // W^T, rounded + k-permuted

// ======================= helpers =======================
__device__ __forceinline__ uint32_t f2tf32(float f) {
    uint32_t r;
    asm("cvt.rna.tf32.f32 %0, %1;" : "=r"(r) : "f"(f));
    return r;
}
__device__ __forceinline__ float roundtf(float f) { return __uint_as_float(f2tf32(f)); }

__device__ __forceinline__ void cp_async16(uint32_t saddr, const void* g) {
    asm volatile("cp.async.cg.shared.global [%0], [%1], 16;\n" :: "r"(saddr), "l"(g));
}
__device__ __forceinline__ void cp_commit() {
    asm volatile("cp.async.commit_group;\n" ::: "memory");
}
__device__ __forceinline__ void cp_wait1() {
    asm volatile("cp.async.wait_group 1;\n" ::: "memory");
}

__device__ __forceinline__ void mma_tf32(
    float& c0, float& c1, float& c2, float& c3,
    uint32_t a0, uint32_t a1, uint32_t a2, uint32_t a3,
    uint32_t b0, uint32_t b1)
{
    asm volatile(
        "mma.sync.aligned.m16n8k8.row.col.f32.tf32.tf32.f32 "
        "{%0,%1,%2,%3},{%4,%5,%6,%7},{%8,%9},{%0,%1,%2,%3};"
        : "+f"(c0), "+f"(c1), "+f"(c2), "+f"(c3)
        : "r"(a0), "r"(a1), "r"(a2), "r"(a3), "r"(b0), "r"(b1));
}

// ======================= TF32 tensor GEMM =======================
// C[m][n] = A[m][:] . BT[n][:] + bias[n].
// A: [M,2048] row-major, tf32-rounded, k-permuted per 8-group {0,4,1,5,2,6,3,7}.
// BT: [N,2048] row-major (W^T), same rounding/permutation.
// BM=BN=128, BK=32, 256 threads = 8 warps (2x4), warp tile 64x32.
#define RSTRIDE 36                     // row stride in floats (32 + 4 pad)
#define STG_F   (128 * RSTRIDE)        // floats per operand per stage (4608)
#define GEMM_SMEM_BYTES (4 * STG_F * 4)  // A[2] + B[2] = 73728 B

template <bool HEAD_STORE>
__global__ __launch_bounds__(256, 2) void gemm_tf32(
    const float* __restrict__ A, const float* __restrict__ BT,
    const float* __restrict__ bias, float* __restrict__ C)
{
    extern __shared__ float sm[];
    // layout: As[2][4608], Bs[2][4608]
    const int tid  = threadIdx.x;
    const int lane = tid & 31;
    const int warp = tid >> 5;
    const int wm   = warp >> 2;          // 0..1
    const int wn   = warp & 3;           // 0..3
    const int g    = lane >> 2;          // 0..7
    const int t    = lane & 3;           // 0..3
    const int m0   = blockIdx.y * 128;
    const int n0   = blockIdx.x * 128;

    // cp.async geometry: 4 chunks of 16B per operand per thread
    int crow[4], cseg[4];
#pragma unroll
    for (int j = 0; j < 4; j++) {
        int cid = tid + j * 256;          // 0..1023
        crow[j] = cid >> 3;               // 0..127
        cseg[j] = (cid & 7) * 4;          // float offset 0,4,...,28
    }

    float acc[4][4][4];
#pragma unroll
    for (int i = 0; i < 4; i++)
#pragma unroll
        for (int j = 0; j < 4; j++)
#pragma unroll
            for (int e = 0; e < 4; e++) acc[i][j][e] = 0.f;

    auto load_stage = [&](int s, int k0) {
        float* as = sm + s * STG_F;
        float* bs = sm + 2 * STG_F + s * STG_F;
#pragma unroll
        for (int j = 0; j < 4; j++) {
            uint32_t sa = (uint32_t)__cvta_generic_to_shared(&as[crow[j] * RSTRIDE + cseg[j]]);
            cp_async16(sa, &A[(size_t)(m0 + crow[j]) * HIDDEN + k0 + cseg[j]]);
            uint32_t sb = (uint32_t)__cvta_generic_to_shared(&bs[crow[j] * RSTRIDE + cseg[j]]);
            cp_async16(sb, &BT[(size_t)(n0 + crow[j]) * HIDDEN + k0 + cseg[j]]);
        }
        cp_commit();
    };

    const int niter = HIDDEN / 32;   // 64
    load_stage(0, 0);

    for (int it = 0; it < niter; it++) {
        const int buf = it & 1;
        if (it + 1 < niter) load_stage(buf ^ 1, (it + 1) * 32);
        else cp_commit();    // empty group keeps wait1 semantics
        cp_wait1();
        __syncthreads();

        const float* as = sm + buf * STG_F;
        const float* bs = sm + 2 * STG_F + buf * STG_F;

#pragma unroll
        for (int ks = 0; ks < 4; ks++) {
            const int ko = ks * 8 + 2 * t;
            float2 a02[4], a13[4], b01[4];
#pragma unroll
            for (int mf = 0; mf < 4; mf++) {
                const float* pa = as + (wm * 64 + mf * 16 + g) * RSTRIDE + ko;
                a02[mf] = *(const float2*)pa;
                a13[mf] = *(const float2*)(pa + 8 * RSTRIDE);
            }
#pragma unroll
            for (int nf = 0; nf < 4; nf++) {
                const float* pb = bs + (wn * 32 + nf * 8 + g) * RSTRIDE + ko;
                b01[nf] = *(const float2*)pb;
            }
#pragma unroll
            for (int mf = 0; mf < 4; mf++)
#pragma unroll
                for (int nf = 0; nf < 4; nf++)
                    mma_tf32(acc[mf][nf][0], acc[mf][nf][1], acc[mf][nf][2], acc[mf][nf][3],
                             __float_as_uint(a02[mf].x), __float_as_uint(a13[mf].x),
                             __float_as_uint(a02[mf].y), __float_as_uint(a13[mf].y),
                             __float_as_uint(b01[nf].x), __float_as_uint(b01[nf].y));
        }
        __syncthreads();
    }

    // epilogue: c0->(r,c) c1->(r,c+1) c2->(r+8,c) c3->(r+8,c+1)
#pragma unroll
    for (int mf = 0; mf < 4; mf++) {
        int row0 = m0 + wm * 64 + mf * 16 + g;
#pragma unroll
        for (int nf = 0; nf < 4; nf++) {
            int col = n0 + wn * 32 + nf * 8 + 2 * t;
            float b0 = bias[col], b1 = bias[col + 1];
            float v00 = acc[mf][nf][0] + b0, v01 = acc[mf][nf][1] + b1;
            float v10 = acc[mf][nf][2] + b0, v11 = acc[mf][nf][3] + b1;
            if (HEAD_STORE) {
                int bi = row0 >> 11, s = row0 & (SEQ - 1);
                int h  = col >> 7,  d = col & (HEAD_DIM - 1);
                size_t base0 = ((size_t)(bi * NUM_HEADS + h) * SEQ + s) * HEAD_DIM + d;
                *(float2*)&C[base0] = make_float2(v00, v01);
                int row1 = row0 + 8;
                int s1 = row1 & (SEQ - 1); int bi1 = row1 >> 11;
                size_t base1 = ((size_t)(bi1 * NUM_HEADS + h) * SEQ + s1) * HEAD_DIM + d;
                *(float2*)&C[base1] = make_float2(v10, v11);
            } else {
                *(float2*)&C[(size_t)row0 * HIDDEN + col]       = make_float2(v00, v01);
                *(float2*)&C[(size_t)(row0 + 8) * HIDDEN + col] = make_float2(v10, v11);
            }
        }
    }
}

// ======================= prep kernels =======================
// out[8g + p] = round_tf32(in[8g + o(p)]), o = {0,4,1,5,2,6,3,7}
__global__ __launch_bounds__(256) void permute_round_kernel(
    const float* __restrict__ in, float* __restrict__ out)
{
    int i = (blockIdx.x * 256 + threadIdx.x) * 8;
    float4 u = *(const float4*)&in[i];
    float4 v = *(const float4*)&in[i + 4];
    float4 o1 = make_float4(roundtf(u.x), roundtf(v.x), roundtf(u.y), roundtf(v.y));
    float4 o2 = make_float4(roundtf(u.z), roundtf(v.z), roundtf(u.w), roundtf(v.w));
    *(float4*)&out[i]     = o1;
    *(float4*)&out[i + 4] = o2;
}

// WT[n][perm(k)] = round_tf32(W[k][n])
__global__ __launch_bounds__(256) void transpose_round_kernel(
    const float* __restrict__ W, float* __restrict__ WT)
{
    __shared__ float tle[32][33];
    int x  = blockIdx.x * 32 + threadIdx.x;    // n on read
    int y0 = blockIdx.y * 32 + threadIdx.y;    // k on read
#pragma unroll
    for (int i = 0; i < 4; i++)
        tle[threadIdx.y + i * 8][threadIdx.x] = W[(size_t)(y0 + i * 8) * HIDDEN + x];
    __syncthreads();
    int xk = blockIdx.y * 32 + threadIdx.x;    // k on write
    int o  = xk & 7;
    int p  = (o < 4) ? (2 * o) : (2 * o - 7);
    int xkp = (xk & ~7) | p;
    int yn = blockIdx.x * 32 + threadIdx.y;    // n on write
#pragma unroll
    for (int i = 0; i < 4; i++)
        WT[(size_t)(yn + i * 8) * HIDDEN + xkp] =
            roundtf(tle[threadIdx.x][threadIdx.y + i * 8]);
}

// ======================= RoPE (in-place on [B,H,S,D]) =======================
__global__ __launch_bounds__(256) void rope_kernel(float* __restrict__ T)
{
    int idx = blockIdx.x * blockDim.x + threadIdx.x;
    int d   = idx & 63;
    int row = idx >> 6;
    int s   = row & (SEQ - 1);

    float inv = powf(10000.0f, -(float)(2 * d) / (float)HEAD_DIM);
    float fr  = (float)s * inv;
    float c, sn;
    sincosf(fr, &sn, &c);

    float* p = T + (size_t)row * HEAD_DIM;
    float t1 = p[d];
    float t2 = p[d + 64];
    p[d]      = t1 * c - t2 * sn;
    p[d + 64] = t1 * sn + t2 * c;
}

// ======================= Sliding-window attention =======================
#define QT 64
#define SM_QST 0
#define SM_KST 8192
#define SM_VS  16384
#define SM_SS  24576
#define SM_TOTAL_F (24576 + 64 * 65)
#define SM_ATTN_BYTES (SM_TOTAL_F * 4)

__global__ __launch_bounds__(256) void swattn_kernel(
    const float* __restrict__ Q, const float* __restrict__ K,
    const float* __restrict__ V, const float* __restrict__ kw,
    float* __restrict__ AO)
{
    extern __shared__ float sm[];
    float* Qst = sm + SM_QST;
    float* Kst = sm + SM_KST;
    float* Vs  = sm + SM_VS;
    float* Ss  = sm + SM_SS;

    const int tid = threadIdx.x;
    const int bh  = blockIdx.y;
    const int h   = bh & (NUM_HEADS - 1);
    const int b   = bh >> 4;
    const int q0  = blockIdx.x * QT;

    const float qscale = kw[h] * rsqrtf((float)HEAD_DIM);

    const float* Qb = Q + (size_t)bh * SEQ * HEAD_DIM;
    const float* Kb = K + (size_t)bh * SEQ * HEAD_DIM;
    const float* Vb = V + (size_t)bh * SEQ * HEAD_DIM;

#pragma unroll
    for (int it = 0; it < 8; it++) {
        int lin = tid + it * 256;
        int q   = lin >> 5;
        int d4  = (lin & 31) * 4;
        float4 v = *(const float4*)&Qb[(size_t)(q0 + q) * HEAD_DIM + d4];
        Qst[(d4 + 0) * 64 + q] = v.x * qscale;
        Qst[(d4 + 1) * 64 + q] = v.y * qscale;
        Qst[(d4 + 2) * 64 + q] = v.z * qscale;
        Qst[(d4 + 3) * 64 + q] = v.w * qscale;
    }

    const int r = tid >> 2;
    const int g = tid & 3;
    float mrow = -1e30f;
    float lrow = 0.f;
    float4 acc4[8];
#pragma unroll
    for (int t = 0; t < 8; t++) acc4[t] = make_float4(0.f, 0.f, 0.f, 0.f);

    const int txx = tid & 15;
    const int tyy = tid >> 4;

    int c_start = q0 - WINDOW; if (c_start < 0) c_start = 0;

    for (int k0 = c_start; k0 <= q0; k0 += QT) {
        __syncthreads();

#pragma unroll
        for (int it = 0; it < 8; it++) {
            int lin = tid + it * 256;
            int kq  = lin >> 5;
            int d4  = (lin & 31) * 4;
            float4 kv = *(const float4*)&Kb[(size_t)(k0 + kq) * HEAD_DIM + d4];
            Kst[(d4 + 0) * 64 + kq] = kv.x;
            Kst[(d4 + 1) * 64 + kq] = kv.y;
            Kst[(d4 + 2) * 64 + kq] = kv.z;
            Kst[(d4 + 3) * 64 + kq] = kv.w;
            *(float4*)&Vs[kq * HEAD_DIM + d4] =
                *(const float4*)&Vb[(size_t)(k0 + kq) * HEAD_DIM + d4];
        }
        __syncthreads();

        float sc[4][4];
#pragma unroll
        for (int i = 0; i < 4; i++)
#pragma unroll
            for (int j = 0; j < 4; j++) sc[i][j] = 0.f;

        for (int d = 0; d < HEAD_DIM; d++) {
            float4 a  = *(const float4*)&Qst[d * 64 + tyy * 4];
            float4 bb = *(const float4*)&Kst[d * 64 + txx * 4];
            sc[0][0] += a.x * bb.x; sc[0][1] += a.x * bb.y; sc[0][2] += a.x * bb.z; sc[0][3] += a.x * bb.w;
            sc[1][0] += a.y * bb.x; sc[1][1] += a.y * bb.y; sc[1][2] += a.y * bb.z; sc[1][3] += a.y * bb.w;
            sc[2][0] += a.z * bb.x; sc[2][1] += a.z * bb.y; sc[2][2] += a.z * bb.z; sc[2][3] += a.z * bb.w;
            sc[3][0] += a.w * bb.x; sc[3][1] += a.w * bb.y; sc[3][2] += a.w * bb.z; sc[3][3] += a.w * bb.w;
        }
#pragma unroll
        for (int i = 0; i < 4; i++) {
            int qg = q0 + tyy * 4 + i;
#pragma unroll
            for (int j = 0; j < 4; j++) {
                int kg = k0 + txx * 4 + j;
                bool ok = (kg <= qg) && (kg >= qg - WINDOW);
                Ss[(tyy * 4 + i) * 65 + (txx * 4 + j)] = ok ? sc[i][j] : -1e30f;
            }
        }
        __syncthreads();

        float cmax = -1e30f;
#pragma unroll
        for (int j = 0; j < 16; j++)
            cmax = fmaxf(cmax, Ss[r * 65 + g * 16 + j]);
        cmax = fmaxf(cmax, __shfl_xor_sync(0xffffffffu, cmax, 1));
        cmax = fmaxf(cmax, __shfl_xor_sync(0xffffffffu, cmax, 2));

        float newm = fmaxf(mrow, cmax);
        float rescale = expf(mrow - newm);

        float psum = 0.f;
#pragma unroll
        for (int j = 0; j < 16; j++) {
            float p = expf(Ss[r * 65 + g * 16 + j] - newm);
            Ss[r * 65 + g * 16 + j] = p;
            psum += p;
        }
        psum += __shfl_xor_sync(0xffffffffu, psum, 1);
        psum += __shfl_xor_sync(0xffffffffu, psum, 2);
        lrow = lrow * rescale + psum;
        mrow = newm;
        __syncwarp();

#pragma unroll
        for (int t = 0; t < 8; t++) {
            acc4[t].x *= rescale; acc4[t].y *= rescale;
            acc4[t].z *= rescale; acc4[t].w *= rescale;
        }
        for (int j = 0; j < QT; j++) {
            float p = Ss[r * 65 + j];
#pragma unroll
            for (int t = 0; t < 8; t++) {
                float4 v = *(const float4*)&Vs[j * HEAD_DIM + g * 4 + t * 16];
                acc4[t].x += p * v.x;
                acc4[t].y += p * v.y;
                acc4[t].z += p * v.z;
                acc4[t].w += p * v.w;
            }
        }
    }

    float invl = 1.0f / lrow;
    float* op = AO + ((size_t)b * SEQ + q0 + r) * HIDDEN + h * HEAD_DIM + g * 4;
#pragma unroll
    for (int t = 0; t < 8; t++) {
        float4 v;
        v.x = acc4[t].x * invl; v.y = acc4[t].y * invl;
        v.z = acc4[t].z * invl; v.w = acc4[t].w * invl;
        *(float4*)&op[t * 16] = v;
    }
}

// ======================= launch =======================
extern "C" void kernel_launch(void* const* d_in, const int* in_sizes, int n_in,
                              void* d_out, int out_size)
{
    const float* x   = (const float*)d_in[0];
    const float* W_Q = (const float*)d_in[1];
    const float* b_Q = (const float*)d_in[2];
    const float* W_K = (const float*)d_in[3];
    const float* b_K = (const float*)d_in[4];
    const float* W_V = (const float*)d_in[5];
    const float* b_V = (const float*)d_in[6];
    const float* W_O = (const float*)d_in[7];
    const float* b_O = (const float*)d_in[8];
    const float* kw  = (const float*)d_in[9];

    float *Q, *K, *V, *AO, *AO2, *WT;
    cudaGetSymbolAddress((void**)&Q,   g_Q);
    cudaGetSymbolAddress((void**)&K,   g_K);
    cudaGetSymbolAddress((void**)&V,   g_V);
    cudaGetSymbolAddress((void**)&AO,  g_AO);
    cudaGetSymbolAddress((void**)&AO2, g_AO2);
    cudaGetSymbolAddress((void**)&WT,  g_WT);

    cudaFuncSetAttribute(gemm_tf32<true>,
                         cudaFuncAttributeMaxDynamicSharedMemorySize, GEMM_SMEM_BYTES);
    cudaFuncSetAttribute(gemm_tf32<false>,
                         cudaFuncAttributeMaxDynamicSharedMemorySize, GEMM_SMEM_BYTES);
    cudaFuncSetAttribute(swattn_kernel,
                         cudaFuncAttributeMaxDynamicSharedMemorySize, SM_ATTN_BYTES);

    // 1. round+permute x -> AO  (x_perm)
    permute_round_kernel<<<M_ROWS * HIDDEN / (256 * 8), 256>>>(x, AO);

    dim3 tg(HIDDEN / 32, HIDDEN / 32);
    dim3 tb(32, 8);
    dim3 gg(HIDDEN / 128, M_ROWS / 128);   // (16, 32)

    // 2-4. QKV projections
    transpose_round_kernel<<<tg, tb>>>(W_Q, WT);
    gemm_tf32<true><<<gg, 256, GEMM_SMEM_BYTES>>>(AO, WT, b_Q, Q);
    transpose_round_kernel<<<tg, tb>>>(W_K, WT);
    gemm_tf32<true><<<gg, 256, GEMM_SMEM_BYTES>>>(AO, WT, b_K, K);
    transpose_round_kernel<<<tg, tb>>>(W_V, WT);
    gemm_tf32<true><<<gg, 256, GEMM_SMEM_BYTES>>>(AO, WT, b_V, V);

    // 5. RoPE
    int ropeThreads = BATCH * NUM_HEADS * SEQ * 64;
    rope_kernel<<<ropeThreads / 256, 256>>>(Q);
    rope_kernel<<<ropeThreads / 256, 256>>>(K);

    // 6. attention -> AO (natural order; overwrites x_perm)
    dim3 ga(SEQ / QT, BATCH * NUM_HEADS);
    swattn_kernel<<<ga, 256, SM_ATTN_BYTES>>>(Q, K, V, kw, AO);

    // 7. round+permute AO -> AO2, then O-projection
    permute_round_kernel<<<M_ROWS * HIDDEN / (256 * 8), 256>>>(AO, AO2);
    transpose_round_kernel<<<tg, tb>>>(W_O, WT);
    gemm_tf32<false><<<gg, 256, GEMM_SMEM_BYTES>>>(AO2, WT, b_O, (float*)d_out);
}

// round 5
// speedup vs baseline: 1.5806x; 1.5806x over previous
#include <cuda_runtime.h>
#include <cuda_fp16.h>
#include <math.h>
#include <stdint.h>

#define HIDDEN    2048
#define NUM_HEADS 16
#define HEAD_DIM  128
#define WINDOW    256
#define BATCH     2
#define SEQ       2048
#define M_ROWS    (BATCH * SEQ)        // 4096

// -------- scratch (static device buffers; no allocation allowed) --------
__device__ float  g_Q[BATCH * NUM_HEADS * SEQ * HEAD_DIM];
__device__ float  g_K[BATCH * NUM_HEADS * SEQ * HEAD_DIM];
__device__ float  g_V[BATCH * NUM_HEADS * SEQ * HEAD_DIM];
__device__ float  g_AO[BATCH * SEQ * HIDDEN];       // attention output (f32)
__device__ __half g_Xh[M_ROWS * HIDDEN];            // x, fp16, k-permuted
__device__ __half g_AOh[M_ROWS * HIDDEN];           // attn out, fp16, k-permuted
__device__ __half g_WTh[HIDDEN * HIDDEN];           // W^T, fp16, k-permuted

// ======================= helpers =======================
__device__ __forceinline__ void cp_async16(uint32_t saddr, const void* g) {
    asm volatile("cp.async.cg.shared.global [%0], [%1], 16;\n" :: "r"(saddr), "l"(g));
}
__device__ __forceinline__ void cp_commit() {
    asm volatile("cp.async.commit_group;\n" ::: "memory");
}
__device__ __forceinline__ void cp_wait1() {
    asm volatile("cp.async.wait_group 1;\n" ::: "memory");
}

__device__ __forceinline__ void mma_f16(
    float& c0, float& c1, float& c2, float& c3,
    uint32_t a0, uint32_t a1, uint32_t a2, uint32_t a3,
    uint32_t b0, uint32_t b1)
{
    asm volatile(
        "mma.sync.aligned.m16n8k16.row.col.f32.f16.f16.f32 "
        "{%0,%1,%2,%3},{%4,%5,%6,%7},{%8,%9},{%0,%1,%2,%3};"
        : "+f"(c0), "+f"(c1), "+f"(c2), "+f"(c3)
        : "r"(a0), "r"(a1), "r"(a2), "r"(a3), "r"(b0), "r"(b1));
}

// ======================= FP16 tensor GEMM =======================
// C[m][n] = A[m][:] . BT[n][:] + bias[n]  (fp32 accumulate).
// A: [M,2048] half, k-permuted per 16-group (pos 4t..4t+3 = orig 2t,2t+1,2t+8,2t+9).
// BT: [N,2048] half (W^T), same permutation.
// BM=BN=128, BK=64 (halfs), 256 threads = 8 warps (2x4), warp tile 64x32.
#define ROWH  80                       // smem row stride in halfs (40 words ≡ 8 mod 32)
#define OPSTH (128 * ROWH)             // halfs per operand per stage (10240)
#define GEMM_SMEM_BYTES (4 * OPSTH * 2)  // A[2]+B[2] = 81920 B

template <bool HEAD_STORE>
__global__ __launch_bounds__(256, 2) void gemm_f16(
    const __half* __restrict__ A, const __half* __restrict__ BT,
    const float* __restrict__ bias, float* __restrict__ C)
{
    extern __shared__ __half smh[];
    const int tid  = threadIdx.x;
    const int lane = tid & 31;
    const int warp = tid >> 5;
    const int wm   = warp >> 2;          // 0..1
    const int wn   = warp & 3;           // 0..3
    const int g    = lane >> 2;          // 0..7
    const int t    = lane & 3;           // 0..3
    const int m0   = blockIdx.y * 128;
    const int n0   = blockIdx.x * 128;

    // cp.async geometry: 64 halfs = 128B per row = 8 chunks of 16B
    int crow[4], cseg[4];
#pragma unroll
    for (int j = 0; j < 4; j++) {
        int cid = tid + j * 256;          // 0..1023
        crow[j] = cid >> 3;               // 0..127
        cseg[j] = (cid & 7) * 8;          // half offset 0,8,...,56
    }

    float acc[4][4][4];
#pragma unroll
    for (int i = 0; i < 4; i++)
#pragma unroll
        for (int j = 0; j < 4; j++)
#pragma unroll
            for (int e = 0; e < 4; e++) acc[i][j][e] = 0.f;

    auto load_stage = [&](int s, int k0) {
        __half* as = smh + s * OPSTH;
        __half* bs = smh + 2 * OPSTH + s * OPSTH;
#pragma unroll
        for (int j = 0; j < 4; j++) {
            uint32_t sa = (uint32_t)__cvta_generic_to_shared(&as[crow[j] * ROWH + cseg[j]]);
            cp_async16(sa, &A[(size_t)(m0 + crow[j]) * HIDDEN + k0 + cseg[j]]);
            uint32_t sb = (uint32_t)__cvta_generic_to_shared(&bs[crow[j] * ROWH + cseg[j]]);
            cp_async16(sb, &BT[(size_t)(n0 + crow[j]) * HIDDEN + k0 + cseg[j]]);
        }
        cp_commit();
    };

    const int niter = HIDDEN / 64;   // 32
    load_stage(0, 0);

    for (int it = 0; it < niter; it++) {
        const int buf = it & 1;
        if (it + 1 < niter) load_stage(buf ^ 1, (it + 1) * 64);
        else cp_commit();    // empty group keeps wait1 semantics
        cp_wait1();
        __syncthreads();

        const __half* as = smh + buf * OPSTH;
        const __half* bs = smh + 2 * OPSTH + buf * OPSTH;

#pragma unroll
        for (int ks = 0; ks < 4; ks++) {
            const int ko = ks * 16 + 4 * t;
            uint2 alo[4], ahi[4], bfr[4];
#pragma unroll
            for (int mf = 0; mf < 4; mf++) {
                const __half* pa = as + (wm * 64 + mf * 16 + g) * ROWH + ko;
                alo[mf] = *(const uint2*)pa;                 // (g,   2t..) , (g,   2t+8..)
                ahi[mf] = *(const uint2*)(pa + 8 * ROWH);    // (g+8, 2t..) , (g+8, 2t+8..)
            }
#pragma unroll
            for (int nf = 0; nf < 4; nf++) {
                const __half* pb = bs + (wn * 32 + nf * 8 + g) * ROWH + ko;
                bfr[nf] = *(const uint2*)pb;                 // b0, b1
            }
#pragma unroll
            for (int mf = 0; mf < 4; mf++)
#pragma unroll
                for (int nf = 0; nf < 4; nf++)
                    mma_f16(acc[mf][nf][0], acc[mf][nf][1], acc[mf][nf][2], acc[mf][nf][3],
                            alo[mf].x, ahi[mf].x, alo[mf].y, ahi[mf].y,
                            bfr[nf].x, bfr[nf].y);
        }
        __syncthreads();
    }

    // epilogue: c0->(r,c) c1->(r,c+1) c2->(r+8,c) c3->(r+8,c+1)
#pragma unroll
    for (int mf = 0; mf < 4; mf++) {
        int row0 = m0 + wm * 64 + mf * 16 + g;
#pragma unroll
        for (int nf = 0; nf < 4; nf++) {
            int col = n0 + wn * 32 + nf * 8 + 2 * t;
            float b0 = bias[col], b1 = bias[col + 1];
            float v00 = acc[mf][nf][0] + b0, v01 = acc[mf][nf][1] + b1;
            float v10 = acc[mf][nf][2] + b0, v11 = acc[mf][nf][3] + b1;
            if (HEAD_STORE) {
                int bi = row0 >> 11, s = row0 & (SEQ - 1);
                int h  = col >> 7,  d = col & (HEAD_DIM - 1);
                size_t base0 = ((size_t)(bi * NUM_HEADS + h) * SEQ + s) * HEAD_DIM + d;
                *(float2*)&C[base0] = make_float2(v00, v01);
                int row1 = row0 + 8;
                int s1 = row1 & (SEQ - 1); int bi1 = row1 >> 11;
                size_t base1 = ((size_t)(bi1 * NUM_HEADS + h) * SEQ + s1) * HEAD_DIM + d;
                *(float2*)&C[base1] = make_float2(v10, v11);
            } else {
                *(float2*)&C[(size_t)row0 * HIDDEN + col]       = make_float2(v00, v01);
                *(float2*)&C[(size_t)(row0 + 8) * HIDDEN + col] = make_float2(v10, v11);
            }
        }
    }
}

// ======================= prep kernels =======================
// f32 -> f16 with per-16-group permutation: dest 4t..4t+3 = src 2t,2t+1,2t+8,2t+9
__global__ __launch_bounds__(256) void convert_perm_kernel(
    const float* __restrict__ in, __half* __restrict__ out)
{
    int i = (blockIdx.x * 256 + threadIdx.x) * 16;
    float4 u0 = *(const float4*)&in[i];
    float4 u1 = *(const float4*)&in[i + 4];
    float4 u2 = *(const float4*)&in[i + 8];
    float4 u3 = *(const float4*)&in[i + 12];
    __half2 h[8];
    h[0] = __floats2half2_rn(u0.x, u0.y);   // s0,s1
    h[1] = __floats2half2_rn(u2.x, u2.y);   // s8,s9
    h[2] = __floats2half2_rn(u0.z, u0.w);   // s2,s3
    h[3] = __floats2half2_rn(u2.z, u2.w);   // s10,s11
    h[4] = __floats2half2_rn(u1.x, u1.y);   // s4,s5
    h[5] = __floats2half2_rn(u3.x, u3.y);   // s12,s13
    h[6] = __floats2half2_rn(u1.z, u1.w);   // s6,s7
    h[7] = __floats2half2_rn(u3.z, u3.w);   // s14,s15
    *(uint4*)&out[i]     = *(uint4*)&h[0];
    *(uint4*)&out[i + 8] = *(uint4*)&h[4];
}

// WT[n][perm(k)] = half(W[k][n])
__global__ __launch_bounds__(256) void transpose_convert_kernel(
    const float* __restrict__ W, __half* __restrict__ WT)
{
    __shared__ float tle[32][33];
    int x  = blockIdx.x * 32 + threadIdx.x;    // n on read
    int y0 = blockIdx.y * 32 + threadIdx.y;    // k on read
#pragma unroll
    for (int i = 0; i < 4; i++)
        tle[threadIdx.y + i * 8][threadIdx.x] = W[(size_t)(y0 + i * 8) * HIDDEN + x];
    __syncthreads();
    int xk = blockIdx.y * 32 + threadIdx.x;    // k on write
    int q  = xk & 15;
    int newk = (xk & ~15) + 4 * ((q & 7) >> 1) + 2 * (q >> 3) + (q & 1);
    int yn = blockIdx.x * 32 + threadIdx.y;    // n on write
#pragma unroll
    for (int i = 0; i < 4; i++)
        WT[(size_t)(yn + i * 8) * HIDDEN + newk] =
            __float2half_rn(tle[threadIdx.x][threadIdx.y + i * 8]);
}

// ======================= RoPE (in-place on [B,H,S,D]) =======================
__global__ __launch_bounds__(256) void rope_kernel(float* __restrict__ T)
{
    int idx = blockIdx.x * blockDim.x + threadIdx.x;
    int d   = idx & 63;
    int row = idx >> 6;
    int s   = row & (SEQ - 1);

    float inv = powf(10000.0f, -(float)(2 * d) / (float)HEAD_DIM);
    float fr  = (float)s * inv;
    float c, sn;
    sincosf(fr, &sn, &c);

    float* p = T + (size_t)row * HEAD_DIM;
    float t1 = p[d];
    float t2 = p[d + 64];
    p[d]      = t1 * c - t2 * sn;
    p[d + 64] = t1 * sn + t2 * c;
}

// ======================= Sliding-window attention =======================
#define QT 64
#define SM_QST 0
#define SM_KST 8192
#define SM_VS  16384
#define SM_SS  24576
#define SM_TOTAL_F (24576 + 64 * 65)
#define SM_ATTN_BYTES (SM_TOTAL_F * 4)

__global__ __launch_bounds__(256) void swattn_kernel(
    const float* __restrict__ Q, const float* __restrict__ K,
    const float* __restrict__ V, const float* __restrict__ kw,
    float* __restrict__ AO)
{
    extern __shared__ float sm[];
    float* Qst = sm + SM_QST;
    float* Kst = sm + SM_KST;
    float* Vs  = sm + SM_VS;
    float* Ss  = sm + SM_SS;

    const int tid = threadIdx.x;
    const int bh  = blockIdx.y;
    const int h   = bh & (NUM_HEADS - 1);
    const int b   = bh >> 4;
    const int q0  = blockIdx.x * QT;

    const float qscale = kw[h] * rsqrtf((float)HEAD_DIM);

    const float* Qb = Q + (size_t)bh * SEQ * HEAD_DIM;
    const float* Kb = K + (size_t)bh * SEQ * HEAD_DIM;
    const float* Vb = V + (size_t)bh * SEQ * HEAD_DIM;

#pragma unroll
    for (int it = 0; it < 8; it++) {
        int lin = tid + it * 256;
        int q   = lin >> 5;
        int d4  = (lin & 31) * 4;
        float4 v = *(const float4*)&Qb[(size_t)(q0 + q) * HEAD_DIM + d4];
        Qst[(d4 + 0) * 64 + q] = v.x * qscale;
        Qst[(d4 + 1) * 64 + q] = v.y * qscale;
        Qst[(d4 + 2) * 64 + q] = v.z * qscale;
        Qst[(d4 + 3) * 64 + q] = v.w * qscale;
    }

    const int r = tid >> 2;
    const int g = tid & 3;
    float mrow = -1e30f;
    float lrow = 0.f;
    float4 acc4[8];
#pragma unroll
    for (int t = 0; t < 8; t++) acc4[t] = make_float4(0.f, 0.f, 0.f, 0.f);

    const int txx = tid & 15;
    const int tyy = tid >> 4;

    int c_start = q0 - WINDOW; if (c_start < 0) c_start = 0;

    for (int k0 = c_start; k0 <= q0; k0 += QT) {
        __syncthreads();

#pragma unroll
        for (int it = 0; it < 8; it++) {
            int lin = tid + it * 256;
            int kq  = lin >> 5;
            int d4  = (lin & 31) * 4;
            float4 kv = *(const float4*)&Kb[(size_t)(k0 + kq) * HEAD_DIM + d4];
            Kst[(d4 + 0) * 64 + kq] = kv.x;
            Kst[(d4 + 1) * 64 + kq] = kv.y;
            Kst[(d4 + 2) * 64 + kq] = kv.z;
            Kst[(d4 + 3) * 64 + kq] = kv.w;
            *(float4*)&Vs[kq * HEAD_DIM + d4] =
                *(const float4*)&Vb[(size_t)(k0 + kq) * HEAD_DIM + d4];
        }
        __syncthreads();

        float sc[4][4];
#pragma unroll
        for (int i = 0; i < 4; i++)
#pragma unroll
            for (int j = 0; j < 4; j++) sc[i][j] = 0.f;

        for (int d = 0; d < HEAD_DIM; d++) {
            float4 a  = *(const float4*)&Qst[d * 64 + tyy * 4];
            float4 bb = *(const float4*)&Kst[d * 64 + txx * 4];
            sc[0][0] += a.x * bb.x; sc[0][1] += a.x * bb.y; sc[0][2] += a.x * bb.z; sc[0][3] += a.x * bb.w;
            sc[1][0] += a.y * bb.x; sc[1][1] += a.y * bb.y; sc[1][2] += a.y * bb.z; sc[1][3] += a.y * bb.w;
            sc[2][0] += a.z * bb.x; sc[2][1] += a.z * bb.y; sc[2][2] += a.z * bb.z; sc[2][3] += a.z * bb.w;
            sc[3][0] += a.w * bb.x; sc[3][1] += a.w * bb.y; sc[3][2] += a.w * bb.z; sc[3][3] += a.w * bb.w;
        }
#pragma unroll
        for (int i = 0; i < 4; i++) {
            int qg = q0 + tyy * 4 + i;
#pragma unroll
            for (int j = 0; j < 4; j++) {
                int kg = k0 + txx * 4 + j;
                bool ok = (kg <= qg) && (kg >= qg - WINDOW);
                Ss[(tyy * 4 + i) * 65 + (txx * 4 + j)] = ok ? sc[i][j] : -1e30f;
            }
        }
        __syncthreads();

        float cmax = -1e30f;
#pragma unroll
        for (int j = 0; j < 16; j++)
            cmax = fmaxf(cmax, Ss[r * 65 + g * 16 + j]);
        cmax = fmaxf(cmax, __shfl_xor_sync(0xffffffffu, cmax, 1));
        cmax = fmaxf(cmax, __shfl_xor_sync(0xffffffffu, cmax, 2));

        float newm = fmaxf(mrow, cmax);
        float rescale = expf(mrow - newm);

        float psum = 0.f;
#pragma unroll
        for (int j = 0; j < 16; j++) {
            float p = expf(Ss[r * 65 + g * 16 + j] - newm);
            Ss[r * 65 + g * 16 + j] = p;
            psum += p;
        }
        psum += __shfl_xor_sync(0xffffffffu, psum, 1);
        psum += __shfl_xor_sync(0xffffffffu, psum, 2);
        lrow = lrow * rescale + psum;
        mrow = newm;
        __syncwarp();

#pragma unroll
        for (int t = 0; t < 8; t++) {
            acc4[t].x *= rescale; acc4[t].y *= rescale;
            acc4[t].z *= rescale; acc4[t].w *= rescale;
        }
        for (int j = 0; j < QT; j++) {
            float p = Ss[r * 65 + j];
#pragma unroll
            for (int t = 0; t < 8; t++) {
                float4 v = *(const float4*)&Vs[j * HEAD_DIM + g * 4 + t * 16];
                acc4[t].x += p * v.x;
                acc4[t].y += p * v.y;
                acc4[t].z += p * v.z;
                acc4[t].w += p * v.w;
            }
        }
    }

    float invl = 1.0f / lrow;
    float* op = AO + ((size_t)b * SEQ + q0 + r) * HIDDEN + h * HEAD_DIM + g * 4;
#pragma unroll
    for (int t = 0; t < 8; t++) {
        float4 v;
        v.x = acc4[t].x * invl; v.y = acc4[t].y * invl;
        v.z = acc4[t].z * invl; v.w = acc4[t].w * invl;
        *(float4*)&op[t * 16] = v;
    }
}

// ======================= launch =======================
extern "C" void kernel_launch(void* const* d_in, const int* in_sizes, int n_in,
                              void* d_out, int out_size)
{
    const float* x   = (const float*)d_in[0];
    const float* W_Q = (const float*)d_in[1];
    const float* b_Q = (const float*)d_in[2];
    const float* W_K = (const float*)d_in[3];
    const float* b_K = (const float*)d_in[4];
    const float* W_V = (const float*)d_in[5];
    const float* b_V = (const float*)d_in[6];
    const float* W_O = (const float*)d_in[7];
    const float* b_O = (const float*)d_in[8];
    const float* kw  = (const float*)d_in[9];

    float *Q, *K, *V, *AO;
    __half *Xh, *AOh, *WTh;
    cudaGetSymbolAddress((void**)&Q,   g_Q);
    cudaGetSymbolAddress((void**)&K,   g_K);
    cudaGetSymbolAddress((void**)&V,   g_V);
    cudaGetSymbolAddress((void**)&AO,  g_AO);
    cudaGetSymbolAddress((void**)&Xh,  g_Xh);
    cudaGetSymbolAddress((void**)&AOh, g_AOh);
    cudaGetSymbolAddress((void**)&WTh, g_WTh);

    cudaFuncSetAttribute(gemm_f16<true>,
                         cudaFuncAttributeMaxDynamicSharedMemorySize, GEMM_SMEM_BYTES);
    cudaFuncSetAttribute(gemm_f16<false>,
                         cudaFuncAttributeMaxDynamicSharedMemorySize, GEMM_SMEM_BYTES);
    cudaFuncSetAttribute(swattn_kernel,
                         cudaFuncAttributeMaxDynamicSharedMemorySize, SM_ATTN_BYTES);

    // 1. convert+permute x -> Xh
    convert_perm_kernel<<<M_ROWS * HIDDEN / (256 * 16), 256>>>(x, Xh);

    dim3 tg(HIDDEN / 32, HIDDEN / 32);
    dim3 tb(32, 8);
    dim3 gg(HIDDEN / 128, M_ROWS / 128);   // (16, 32)

    // 2-4. QKV projections
    transpose_convert_kernel<<<tg, tb>>>(W_Q, WTh);
    gemm_f16<true><<<gg, 256, GEMM_SMEM_BYTES>>>(Xh, WTh, b_Q, Q);
    transpose_convert_kernel<<<tg, tb>>>(W_K, WTh);
    gemm_f16<true><<<gg, 256, GEMM_SMEM_BYTES>>>(Xh, WTh, b_K, K);
    transpose_convert_kernel<<<tg, tb>>>(W_V, WTh);
    gemm_f16<true><<<gg, 256, GEMM_SMEM_BYTES>>>(Xh, WTh, b_V, V);

    // 5. RoPE
    int ropeThreads = BATCH * NUM_HEADS * SEQ * 64;
    rope_kernel<<<ropeThreads / 256, 256>>>(Q);
    rope_kernel<<<ropeThreads / 256, 256>>>(K);

    // 6. attention -> AO (f32)
    dim3 ga(SEQ / QT, BATCH * NUM_HEADS);
    swattn_kernel<<<ga, 256, SM_ATTN_BYTES>>>(Q, K, V, kw, AO);

    // 7. convert+permute AO -> AOh, then O-projection
    convert_perm_kernel<<<M_ROWS * HIDDEN / (256 * 16), 256>>>(AO, AOh);
    transpose_convert_kernel<<<tg, tb>>>(W_O, WTh);
    gemm_f16<false><<<gg, 256, GEMM_SMEM_BYTES>>>(AOh, WTh, b_O, (float*)d_out);
}

// round 6
// speedup vs baseline: 3.4872x; 2.2062x over previous
#include <cuda_runtime.h>
#include <cuda_fp16.h>
#include <math.h>
#include <stdint.h>

#define HIDDEN    2048
#define NUM_HEADS 16
#define HEAD_DIM  128
#define WINDOW    256
#define BATCH     2
#define SEQ       2048
#define M_ROWS    (BATCH * SEQ)        // 4096

// -------- scratch (static device buffers; no allocation allowed) --------
__device__ float  g_Qf[BATCH * NUM_HEADS * SEQ * HEAD_DIM];   // f32, pre-rope
__device__ float  g_Kf[BATCH * NUM_HEADS * SEQ * HEAD_DIM];
__device__ __half g_Qh[BATCH * NUM_HEADS * SEQ * HEAD_DIM];   // f16, post-rope, kw-scaled
__device__ __half g_Kh[BATCH * NUM_HEADS * SEQ * HEAD_DIM];
__device__ __half g_Vh[BATCH * NUM_HEADS * SEQ * HEAD_DIM];
__device__ __half g_Xh[M_ROWS * HIDDEN];                       // x, fp16, k-permuted
__device__ __half g_AOh[M_ROWS * HIDDEN];                      // attn out, fp16, k-permuted
__device__ __half g_WTh3[3 * HIDDEN * HIDDEN];                 // W^T x3, fp16, k-permuted

// ======================= helpers =======================
__device__ __forceinline__ uint32_t smem_u32(const void* p) {
    uint32_t a;
    asm("{ .reg .u64 t; cvta.to.shared.u64 t, %1; cvt.u32.u64 %0, t; }" : "=r"(a) : "l"(p));
    return a;
}
__device__ __forceinline__ void cp_async16(uint32_t saddr, const void* g) {
    asm volatile("cp.async.cg.shared.global [%0], [%1], 16;\n" :: "r"(saddr), "l"(g));
}
__device__ __forceinline__ void cp_commit() {
    asm volatile("cp.async.commit_group;\n" ::: "memory");
}
__device__ __forceinline__ void cp_wait1() {
    asm volatile("cp.async.wait_group 1;\n" ::: "memory");
}

__device__ __forceinline__ void mma_f16(
    float& c0, float& c1, float& c2, float& c3,
    uint32_t a0, uint32_t a1, uint32_t a2, uint32_t a3,
    uint32_t b0, uint32_t b1)
{
    asm volatile(
        "mma.sync.aligned.m16n8k16.row.col.f32.f16.f16.f32 "
        "{%0,%1,%2,%3},{%4,%5,%6,%7},{%8,%9},{%0,%1,%2,%3};"
        : "+f"(c0), "+f"(c1), "+f"(c2), "+f"(c3)
        : "r"(a0), "r"(a1), "r"(a2), "r"(a3), "r"(b0), "r"(b1));
}

#define LDMX4(r0, r1, r2, r3, addr) \
    asm volatile("ldmatrix.sync.aligned.m8n8.x4.shared.b16 {%0,%1,%2,%3}, [%4];" \
                 : "=r"(r0), "=r"(r1), "=r"(r2), "=r"(r3) : "r"(addr))
#define LDMX4T(r0, r1, r2, r3, addr) \
    asm volatile("ldmatrix.sync.aligned.m8n8.x4.trans.shared.b16 {%0,%1,%2,%3}, [%4];" \
                 : "=r"(r0), "=r"(r1), "=r"(r2), "=r"(r3) : "r"(addr))

__device__ __forceinline__ uint32_t packh2(float a, float b) {
    __half2 h = __floats2half2_rn(a, b);
    return *(uint32_t*)&h;
}

// ======================= FP16 tensor GEMM (shared body pieces) =======================
#define ROWH  80                        // smem row stride in halfs
#define OPSTH (128 * ROWH)              // halfs per operand per stage
#define GEMM_SMEM_BYTES (4 * OPSTH * 2) // 81920 B

// ---- fused QKV: grid (48, 32); j = bx>>4 selects weight/output ----
__global__ __launch_bounds__(256, 2) void gemm_qkv(
    const __half* __restrict__ A, const __half* __restrict__ BT3,
    const float* __restrict__ bq, const float* __restrict__ bk, const float* __restrict__ bv,
    float* __restrict__ Qf, float* __restrict__ Kf, __half* __restrict__ Vh)
{
    extern __shared__ __half smh[];
    const int tid  = threadIdx.x;
    const int lane = tid & 31;
    const int warp = tid >> 5;
    const int wm   = warp >> 2;
    const int wn   = warp & 3;
    const int g    = lane >> 2;
    const int t    = lane & 3;
    const int j    = blockIdx.x >> 4;          // 0=Q 1=K 2=V
    const int n0   = (blockIdx.x & 15) * 128;
    const int m0   = blockIdx.y * 128;
    const __half* BT = BT3 + (size_t)j * HIDDEN * HIDDEN;
    const float* bias = (j == 0) ? bq : (j == 1) ? bk : bv;

    int crow[4], cseg[4];
#pragma unroll
    for (int jj = 0; jj < 4; jj++) {
        int cid = tid + jj * 256;
        crow[jj] = cid >> 3;
        cseg[jj] = (cid & 7) * 8;
    }

    float acc[4][4][4];
#pragma unroll
    for (int i = 0; i < 4; i++)
#pragma unroll
        for (int jj = 0; jj < 4; jj++)
#pragma unroll
            for (int e = 0; e < 4; e++) acc[i][jj][e] = 0.f;

    auto load_stage = [&](int s, int k0) {
        __half* as = smh + s * OPSTH;
        __half* bs = smh + 2 * OPSTH + s * OPSTH;
#pragma unroll
        for (int jj = 0; jj < 4; jj++) {
            uint32_t sa = (uint32_t)__cvta_generic_to_shared(&as[crow[jj] * ROWH + cseg[jj]]);
            cp_async16(sa, &A[(size_t)(m0 + crow[jj]) * HIDDEN + k0 + cseg[jj]]);
            uint32_t sb = (uint32_t)__cvta_generic_to_shared(&bs[crow[jj] * ROWH + cseg[jj]]);
            cp_async16(sb, &BT[(size_t)(n0 + crow[jj]) * HIDDEN + k0 + cseg[jj]]);
        }
        cp_commit();
    };

    const int niter = HIDDEN / 64;
    load_stage(0, 0);

    for (int it = 0; it < niter; it++) {
        const int buf = it & 1;
        if (it + 1 < niter) load_stage(buf ^ 1, (it + 1) * 64);
        else cp_commit();
        cp_wait1();
        __syncthreads();

        const __half* as = smh + buf * OPSTH;
        const __half* bs = smh + 2 * OPSTH + buf * OPSTH;

#pragma unroll
        for (int ks = 0; ks < 4; ks++) {
            const int ko = ks * 16 + 4 * t;
            uint2 alo[4], ahi[4], bfr[4];
#pragma unroll
            for (int mf = 0; mf < 4; mf++) {
                const __half* pa = as + (wm * 64 + mf * 16 + g) * ROWH + ko;
                alo[mf] = *(const uint2*)pa;
                ahi[mf] = *(const uint2*)(pa + 8 * ROWH);
            }
#pragma unroll
            for (int nf = 0; nf < 4; nf++) {
                const __half* pb = bs + (wn * 32 + nf * 8 + g) * ROWH + ko;
                bfr[nf] = *(const uint2*)pb;
            }
#pragma unroll
            for (int mf = 0; mf < 4; mf++)
#pragma unroll
                for (int nf = 0; nf < 4; nf++)
                    mma_f16(acc[mf][nf][0], acc[mf][nf][1], acc[mf][nf][2], acc[mf][nf][3],
                            alo[mf].x, ahi[mf].x, alo[mf].y, ahi[mf].y,
                            bfr[nf].x, bfr[nf].y);
        }
        __syncthreads();
    }

    const int h = blockIdx.x & 15;   // n-tile == head
#pragma unroll
    for (int mf = 0; mf < 4; mf++) {
        int row0 = m0 + wm * 64 + mf * 16 + g;
        int row1 = row0 + 8;
        int bi0 = row0 >> 11, s0 = row0 & (SEQ - 1);
        int bi1 = row1 >> 11, s1 = row1 & (SEQ - 1);
#pragma unroll
        for (int nf = 0; nf < 4; nf++) {
            int col = n0 + wn * 32 + nf * 8 + 2 * t;
            int d = col & (HEAD_DIM - 1);
            float b0 = bias[col], b1 = bias[col + 1];
            float v00 = acc[mf][nf][0] + b0, v01 = acc[mf][nf][1] + b1;
            float v10 = acc[mf][nf][2] + b0, v11 = acc[mf][nf][3] + b1;
            size_t base0 = ((size_t)(bi0 * NUM_HEADS + h) * SEQ + s0) * HEAD_DIM + d;
            size_t base1 = ((size_t)(bi1 * NUM_HEADS + h) * SEQ + s1) * HEAD_DIM + d;
            if (j == 0) {
                *(float2*)&Qf[base0] = make_float2(v00, v01);
                *(float2*)&Qf[base1] = make_float2(v10, v11);
            } else if (j == 1) {
                *(float2*)&Kf[base0] = make_float2(v00, v01);
                *(float2*)&Kf[base1] = make_float2(v10, v11);
            } else {
                *(uint32_t*)&Vh[base0] = packh2(v00, v01);
                *(uint32_t*)&Vh[base1] = packh2(v10, v11);
            }
        }
    }
}

// ---- generic GEMM (for O projection) ----
__global__ __launch_bounds__(256, 2) void gemm_f16(
    const __half* __restrict__ A, const __half* __restrict__ BT,
    const float* __restrict__ bias, float* __restrict__ C)
{
    extern __shared__ __half smh[];
    const int tid  = threadIdx.x;
    const int lane = tid & 31;
    const int warp = tid >> 5;
    const int wm   = warp >> 2;
    const int wn   = warp & 3;
    const int g    = lane >> 2;
    const int t    = lane & 3;
    const int m0   = blockIdx.y * 128;
    const int n0   = blockIdx.x * 128;

    int crow[4], cseg[4];
#pragma unroll
    for (int jj = 0; jj < 4; jj++) {
        int cid = tid + jj * 256;
        crow[jj] = cid >> 3;
        cseg[jj] = (cid & 7) * 8;
    }

    float acc[4][4][4];
#pragma unroll
    for (int i = 0; i < 4; i++)
#pragma unroll
        for (int jj = 0; jj < 4; jj++)
#pragma unroll
            for (int e = 0; e < 4; e++) acc[i][jj][e] = 0.f;

    auto load_stage = [&](int s, int k0) {
        __half* as = smh + s * OPSTH;
        __half* bs = smh + 2 * OPSTH + s * OPSTH;
#pragma unroll
        for (int jj = 0; jj < 4; jj++) {
            uint32_t sa = (uint32_t)__cvta_generic_to_shared(&as[crow[jj] * ROWH + cseg[jj]]);
            cp_async16(sa, &A[(size_t)(m0 + crow[jj]) * HIDDEN + k0 + cseg[jj]]);
            uint32_t sb = (uint32_t)__cvta_generic_to_shared(&bs[crow[jj] * ROWH + cseg[jj]]);
            cp_async16(sb, &BT[(size_t)(n0 + crow[jj]) * HIDDEN + k0 + cseg[jj]]);
        }
        cp_commit();
    };

    const int niter = HIDDEN / 64;
    load_stage(0, 0);

    for (int it = 0; it < niter; it++) {
        const int buf = it & 1;
        if (it + 1 < niter) load_stage(buf ^ 1, (it + 1) * 64);
        else cp_commit();
        cp_wait1();
        __syncthreads();

        const __half* as = smh + buf * OPSTH;
        const __half* bs = smh + 2 * OPSTH + buf * OPSTH;

#pragma unroll
        for (int ks = 0; ks < 4; ks++) {
            const int ko = ks * 16 + 4 * t;
            uint2 alo[4], ahi[4], bfr[4];
#pragma unroll
            for (int mf = 0; mf < 4; mf++) {
                const __half* pa = as + (wm * 64 + mf * 16 + g) * ROWH + ko;
                alo[mf] = *(const uint2*)pa;
                ahi[mf] = *(const uint2*)(pa + 8 * ROWH);
            }
#pragma unroll
            for (int nf = 0; nf < 4; nf++) {
                const __half* pb = bs + (wn * 32 + nf * 8 + g) * ROWH + ko;
                bfr[nf] = *(const uint2*)pb;
            }
#pragma unroll
            for (int mf = 0; mf < 4; mf++)
#pragma unroll
                for (int nf = 0; nf < 4; nf++)
                    mma_f16(acc[mf][nf][0], acc[mf][nf][1], acc[mf][nf][2], acc[mf][nf][3],
                            alo[mf].x, ahi[mf].x, alo[mf].y, ahi[mf].y,
                            bfr[nf].x, bfr[nf].y);
        }
        __syncthreads();
    }

#pragma unroll
    for (int mf = 0; mf < 4; mf++) {
        int row0 = m0 + wm * 64 + mf * 16 + g;
#pragma unroll
        for (int nf = 0; nf < 4; nf++) {
            int col = n0 + wn * 32 + nf * 8 + 2 * t;
            float b0 = bias[col], b1 = bias[col + 1];
            *(float2*)&C[(size_t)row0 * HIDDEN + col] =
                make_float2(acc[mf][nf][0] + b0, acc[mf][nf][1] + b1);
            *(float2*)&C[(size_t)(row0 + 8) * HIDDEN + col] =
                make_float2(acc[mf][nf][2] + b0, acc[mf][nf][3] + b1);
        }
    }
}

// ======================= prep kernels =======================
__global__ __launch_bounds__(256) void convert_perm_kernel(
    const float* __restrict__ in, __half* __restrict__ out)
{
    int i = (blockIdx.x * 256 + threadIdx.x) * 16;
    float4 u0 = *(const float4*)&in[i];
    float4 u1 = *(const float4*)&in[i + 4];
    float4 u2 = *(const float4*)&in[i + 8];
    float4 u3 = *(const float4*)&in[i + 12];
    __half2 h[8];
    h[0] = __floats2half2_rn(u0.x, u0.y);
    h[1] = __floats2half2_rn(u2.x, u2.y);
    h[2] = __floats2half2_rn(u0.z, u0.w);
    h[3] = __floats2half2_rn(u2.z, u2.w);
    h[4] = __floats2half2_rn(u1.x, u1.y);
    h[5] = __floats2half2_rn(u3.x, u3.y);
    h[6] = __floats2half2_rn(u1.z, u1.w);
    h[7] = __floats2half2_rn(u3.z, u3.w);
    *(uint4*)&out[i]     = *(uint4*)&h[0];
    *(uint4*)&out[i + 8] = *(uint4*)&h[4];
}

__global__ __launch_bounds__(256) void transpose_convert_kernel(
    const float* __restrict__ W, __half* __restrict__ WT)
{
    __shared__ float tle[32][33];
    int x  = blockIdx.x * 32 + threadIdx.x;
    int y0 = blockIdx.y * 32 + threadIdx.y;
#pragma unroll
    for (int i = 0; i < 4; i++)
        tle[threadIdx.y + i * 8][threadIdx.x] = W[(size_t)(y0 + i * 8) * HIDDEN + x];
    __syncthreads();
    int xk = blockIdx.y * 32 + threadIdx.x;
    int q  = xk & 15;
    int newk = (xk & ~15) + 4 * ((q & 7) >> 1) + 2 * (q >> 3) + (q & 1);
    int yn = blockIdx.x * 32 + threadIdx.y;
#pragma unroll
    for (int i = 0; i < 4; i++)
        WT[(size_t)(yn + i * 8) * HIDDEN + newk] =
            __float2half_rn(tle[threadIdx.x][threadIdx.y + i * 8]);
}

// ======================= RoPE: f32 in -> f16 out (optional kw scale) =======================
__global__ __launch_bounds__(256) void rope_half_kernel(
    const float* __restrict__ T, __half* __restrict__ Th,
    const float* __restrict__ kw, int scaled)
{
    int idx = blockIdx.x * blockDim.x + threadIdx.x;
    int d   = idx & 63;
    int row = idx >> 6;
    int s   = row & (SEQ - 1);
    int h   = (row >> 11) & (NUM_HEADS - 1);

    float scale = scaled ? kw[h] * 0.08838834764831845f : 1.0f;

    float inv = powf(10000.0f, -(float)(2 * d) / (float)HEAD_DIM);
    float fr  = (float)s * inv;
    float c, sn;
    sincosf(fr, &sn, &c);

    const float* p = T + (size_t)row * HEAD_DIM;
    float t1 = p[d];
    float t2 = p[d + 64];
    Th[(size_t)row * HEAD_DIM + d]      = __float2half_rn((t1 * c - t2 * sn) * scale);
    Th[(size_t)row * HEAD_DIM + d + 64] = __float2half_rn((t1 * sn + t2 * c) * scale);
}

// ======================= Tensor-core sliding-window attention =======================
// 128 threads (4 warps). Block = (bh, 64-query tile). Warp w owns q rows w*16..+16.
// 64-key chunks, m16n8k16 MMAs, online softmax in fp32.
#define SQH 136
#define ATTN_SMEM_BYTES (3 * 64 * SQH * 2)   // Qs, Ks, Vs

__global__ __launch_bounds__(128) void swattn_mma(
    const __half* __restrict__ Qh, const __half* __restrict__ Kh,
    const __half* __restrict__ Vh, __half* __restrict__ AOh)
{
    extern __shared__ __half smh[];
    __half* Qs = smh;
    __half* Ks = smh + 64 * SQH;
    __half* Vs = smh + 2 * 64 * SQH;

    const int tid  = threadIdx.x;
    const int w    = tid >> 5;
    const int lane = tid & 31;
    const int g    = lane >> 2;
    const int t    = lane & 3;
    const int bh   = blockIdx.y;
    const int q0   = blockIdx.x * 64;
    const int qr   = w * 16;

    const uint32_t qs_b = smem_u32(Qs);
    const uint32_t ks_b = smem_u32(Ks);
    const uint32_t vs_b = smem_u32(Vs);

    // lane-constant ldmatrix geometry
    const int l7 = lane & 7;
    const uint32_t a_addr = qs_b +
        (uint32_t)(((qr + l7 + (lane & 8)) * SQH + ((lane & 16) ? 8 : 0)) * 2);
    const int k_rowc = ((lane >> 4) * 8 + l7);           // + p*16
    const int k_colo = (lane & 8) ? 8 : 0;               // + kk*16
    const int v_rowc = (((lane >> 3) & 1) * 8 + l7);     // + ck*16
    const int v_colc = (lane >> 4) * 8;                  // + dp*16

    // load Q tile
    const __half* Qg = Qh + (size_t)(bh * SEQ + q0) * HEAD_DIM;
#pragma unroll
    for (int it = 0; it < 8; it++) {
        int lin = tid + it * 128;
        int row = lin >> 4, seg = (lin & 15) * 8;
        *(uint4*)&Qs[row * SQH + seg] = *(const uint4*)&Qg[row * HEAD_DIM + seg];
    }

    float m0 = -1e30f, m1 = -1e30f, l0 = 0.f, l1 = 0.f;
    float oacc[16][4];
#pragma unroll
    for (int dn = 0; dn < 16; dn++)
#pragma unroll
        for (int e = 0; e < 4; e++) oacc[dn][e] = 0.f;

    const __half* Kg = Kh + (size_t)bh * SEQ * HEAD_DIM;
    const __half* Vg = Vh + (size_t)bh * SEQ * HEAD_DIM;

    int cs = q0 - WINDOW; if (cs < 0) cs = 0;

    for (int k0 = cs; k0 <= q0; k0 += 64) {
        __syncthreads();
#pragma unroll
        for (int it = 0; it < 8; it++) {
            int lin = tid + it * 128;
            int row = lin >> 4, seg = (lin & 15) * 8;
            *(uint4*)&Ks[row * SQH + seg] = *(const uint4*)&Kg[(size_t)(k0 + row) * HEAD_DIM + seg];
            *(uint4*)&Vs[row * SQH + seg] = *(const uint4*)&Vg[(size_t)(k0 + row) * HEAD_DIM + seg];
        }
        __syncthreads();

        // ---- scores: 16q x 64k, accumulate over d=128 ----
        float sc[8][4];
#pragma unroll
        for (int kg = 0; kg < 8; kg++)
#pragma unroll
            for (int e = 0; e < 4; e++) sc[kg][e] = 0.f;

#pragma unroll
        for (int kk = 0; kk < 8; kk++) {
            uint32_t a0, a1, a2, a3;
            LDMX4(a0, a1, a2, a3, a_addr + kk * 32);   // 16 halfs = 32 B per kk
#pragma unroll
            for (int p = 0; p < 4; p++) {
                uint32_t b0, b1, b2, b3;
                uint32_t kaddr = ks_b +
                    (uint32_t)((((k_rowc + p * 16) * SQH) + kk * 16 + k_colo) * 2);
                LDMX4(b0, b1, b2, b3, kaddr);
                mma_f16(sc[2*p][0], sc[2*p][1], sc[2*p][2], sc[2*p][3],
                        a0, a1, a2, a3, b0, b1);
                mma_f16(sc[2*p+1][0], sc[2*p+1][1], sc[2*p+1][2], sc[2*p+1][3],
                        a0, a1, a2, a3, b2, b3);
            }
        }

        // ---- mask (only boundary chunks) ----
        if (k0 == q0 || k0 == q0 - WINDOW) {
            const int qga = q0 + qr + g;
            const int qgb = qga + 8;
#pragma unroll
            for (int kg = 0; kg < 8; kg++) {
                int key = k0 + kg * 8 + 2 * t;
                if (key     > qga || key     < qga - WINDOW) sc[kg][0] = -1e30f;
                if (key + 1 > qga || key + 1 < qga - WINDOW) sc[kg][1] = -1e30f;
                if (key     > qgb || key     < qgb - WINDOW) sc[kg][2] = -1e30f;
                if (key + 1 > qgb || key + 1 < qgb - WINDOW) sc[kg][3] = -1e30f;
            }
        }

        // ---- online softmax ----
        float mx0 = -1e30f, mx1 = -1e30f;
#pragma unroll
        for (int kg = 0; kg < 8; kg++) {
            mx0 = fmaxf(mx0, fmaxf(sc[kg][0], sc[kg][1]));
            mx1 = fmaxf(mx1, fmaxf(sc[kg][2], sc[kg][3]));
        }
        mx0 = fmaxf(mx0, __shfl_xor_sync(0xffffffffu, mx0, 1));
        mx0 = fmaxf(mx0, __shfl_xor_sync(0xffffffffu, mx0, 2));
        mx1 = fmaxf(mx1, __shfl_xor_sync(0xffffffffu, mx1, 1));
        mx1 = fmaxf(mx1, __shfl_xor_sync(0xffffffffu, mx1, 2));

        float nm0 = fmaxf(m0, mx0), nm1 = fmaxf(m1, mx1);
        float rs0 = __expf(m0 - nm0), rs1 = __expf(m1 - nm1);

        float s0 = 0.f, s1 = 0.f;
        uint32_t ph[8][2];
#pragma unroll
        for (int kg = 0; kg < 8; kg++) {
            float p0 = __expf(sc[kg][0] - nm0);
            float p1 = __expf(sc[kg][1] - nm0);
            float p2 = __expf(sc[kg][2] - nm1);
            float p3 = __expf(sc[kg][3] - nm1);
            s0 += p0 + p1;
            s1 += p2 + p3;
            ph[kg][0] = packh2(p0, p1);
            ph[kg][1] = packh2(p2, p3);
        }
        s0 += __shfl_xor_sync(0xffffffffu, s0, 1);
        s0 += __shfl_xor_sync(0xffffffffu, s0, 2);
        s1 += __shfl_xor_sync(0xffffffffu, s1, 1);
        s1 += __shfl_xor_sync(0xffffffffu, s1, 2);

        l0 = l0 * rs0 + s0;
        l1 = l1 * rs1 + s1;
        m0 = nm0; m1 = nm1;

#pragma unroll
        for (int dn = 0; dn < 16; dn++) {
            oacc[dn][0] *= rs0; oacc[dn][1] *= rs0;
            oacc[dn][2] *= rs1; oacc[dn][3] *= rs1;
        }

        // ---- PV: O += P[16x64] @ V[64x128] ----
#pragma unroll
        for (int ck = 0; ck < 4; ck++) {
            uint32_t pa0 = ph[2*ck][0], pa1 = ph[2*ck][1];
            uint32_t pa2 = ph[2*ck+1][0], pa3 = ph[2*ck+1][1];
#pragma unroll
            for (int dp = 0; dp < 8; dp++) {
                uint32_t v0, v1, v2, v3;
                uint32_t vaddr = vs_b +
                    (uint32_t)((((v_rowc + ck * 16) * SQH) + dp * 16 + v_colc) * 2);
                LDMX4T(v0, v1, v2, v3, vaddr);
                mma_f16(oacc[2*dp][0], oacc[2*dp][1], oacc[2*dp][2], oacc[2*dp][3],
                        pa0, pa1, pa2, pa3, v0, v1);
                mma_f16(oacc[2*dp+1][0], oacc[2*dp+1][1], oacc[2*dp+1][2], oacc[2*dp+1][3],
                        pa0, pa1, pa2, pa3, v2, v3);
            }
        }
    }

    // ---- epilogue: normalize and store fp16 k-permuted to AOh ----
    float inv0 = 1.f / l0, inv1 = 1.f / l1;
    const int b = bh >> 4, h = bh & (NUM_HEADS - 1);
    size_t rowa = (size_t)(b * SEQ + q0 + qr + g) * HIDDEN;
    size_t rowb = rowa + (size_t)8 * HIDDEN;
#pragma unroll
    for (int dn = 0; dn < 16; dn++) {
        int a = dn & 1;
        int col = h * 128 + (dn >> 1) * 16 + 4 * t + 2 * a;
        *(uint32_t*)&AOh[rowa + col] = packh2(oacc[dn][0] * inv0, oacc[dn][1] * inv0);
        *(uint32_t*)&AOh[rowb + col] = packh2(oacc[dn][2] * inv1, oacc[dn][3] * inv1);
    }
}

// ======================= launch =======================
extern "C" void kernel_launch(void* const* d_in, const int* in_sizes, int n_in,
                              void* d_out, int out_size)
{
    const float* x   = (const float*)d_in[0];
    const float* W_Q = (const float*)d_in[1];
    const float* b_Q = (const float*)d_in[2];
    const float* W_K = (const float*)d_in[3];
    const float* b_K = (const float*)d_in[4];
    const float* W_V = (const float*)d_in[5];
    const float* b_V = (const float*)d_in[6];
    const float* W_O = (const float*)d_in[7];
    const float* b_O = (const float*)d_in[8];
    const float* kw  = (const float*)d_in[9];

    float *Qf, *Kf;
    __half *Qh, *Kh, *Vh, *Xh, *AOh, *WTh3;
    cudaGetSymbolAddress((void**)&Qf,   g_Qf);
    cudaGetSymbolAddress((void**)&Kf,   g_Kf);
    cudaGetSymbolAddress((void**)&Qh,   g_Qh);
    cudaGetSymbolAddress((void**)&Kh,   g_Kh);
    cudaGetSymbolAddress((void**)&Vh,   g_Vh);
    cudaGetSymbolAddress((void**)&Xh,   g_Xh);
    cudaGetSymbolAddress((void**)&AOh,  g_AOh);
    cudaGetSymbolAddress((void**)&WTh3, g_WTh3);

    cudaFuncSetAttribute(gemm_qkv,
                         cudaFuncAttributeMaxDynamicSharedMemorySize, GEMM_SMEM_BYTES);
    cudaFuncSetAttribute(gemm_f16,
                         cudaFuncAttributeMaxDynamicSharedMemorySize, GEMM_SMEM_BYTES);
    cudaFuncSetAttribute(swattn_mma,
                         cudaFuncAttributeMaxDynamicSharedMemorySize, ATTN_SMEM_BYTES);

    // 1. convert+permute x
    convert_perm_kernel<<<M_ROWS * HIDDEN / (256 * 16), 256>>>(x, Xh);

    dim3 tg(HIDDEN / 32, HIDDEN / 32);
    dim3 tb(32, 8);

    // 2. transpose all three weights, then fused QKV GEMM
    transpose_convert_kernel<<<tg, tb>>>(W_Q, WTh3);
    transpose_convert_kernel<<<tg, tb>>>(W_K, WTh3 + (size_t)HIDDEN * HIDDEN);
    transpose_convert_kernel<<<tg, tb>>>(W_V, WTh3 + (size_t)2 * HIDDEN * HIDDEN);
    dim3 gq(48, M_ROWS / 128);
    gemm_qkv<<<gq, 256, GEMM_SMEM_BYTES>>>(Xh, WTh3, b_Q, b_K, b_V, Qf, Kf, Vh);

    // 3. RoPE + convert (Q scaled by kw*rsqrt(d))
    int ropeThreads = BATCH * NUM_HEADS * SEQ * 64;
    rope_half_kernel<<<ropeThreads / 256, 256>>>(Qf, Qh, kw, 1);
    rope_half_kernel<<<ropeThreads / 256, 256>>>(Kf, Kh, kw, 0);

    // 4. tensor-core attention -> AOh (fp16, k-permuted)
    dim3 ga(SEQ / 64, BATCH * NUM_HEADS);
    swattn_mma<<<ga, 128, ATTN_SMEM_BYTES>>>(Qh, Kh, Vh, AOh);

    // 5. O projection
    transpose_convert_kernel<<<tg, tb>>>(W_O, WTh3);
    dim3 go(HIDDEN / 128, M_ROWS / 128);
    gemm_f16<<<go, 256, GEMM_SMEM_BYTES>>>(AOh, WTh3, b_O, (float*)d_out);
}

// round 7
// speedup vs baseline: 3.6429x; 1.0446x over previous
#include <cuda_runtime.h>
#include <cuda_fp16.h>
#include <math.h>
#include <stdint.h>

#define HIDDEN    2048
#define NUM_HEADS 16
#define HEAD_DIM  128
#define WINDOW    256
#define BATCH     2
#define SEQ       2048
#define M_ROWS    (BATCH * SEQ)        // 4096

// -------- scratch (static device buffers; no allocation allowed) --------
__device__ __half g_Qh[BATCH * NUM_HEADS * SEQ * HEAD_DIM];   // f16 post-rope, kw-scaled
__device__ __half g_Kh[BATCH * NUM_HEADS * SEQ * HEAD_DIM];   // f16 post-rope
__device__ __half g_Vh[BATCH * NUM_HEADS * SEQ * HEAD_DIM];
__device__ __half g_Xh[M_ROWS * HIDDEN];                       // x, fp16, k-permuted
__device__ __half g_AOh[M_ROWS * HIDDEN];                      // attn out, fp16, k-permuted
__device__ __half g_WTh4[4 * HIDDEN * HIDDEN];                 // W^T x4, fp16, k-permuted
__device__ float2 g_rope[SEQ * 64];                            // (cos, sin) per (s, d-pair)

// ======================= helpers =======================
__device__ __forceinline__ uint32_t smem_u32(const void* p) {
    uint32_t a;
    asm("{ .reg .u64 t; cvta.to.shared.u64 t, %1; cvt.u32.u64 %0, t; }" : "=r"(a) : "l"(p));
    return a;
}
__device__ __forceinline__ void cp_async16(uint32_t saddr, const void* g) {
    asm volatile("cp.async.cg.shared.global [%0], [%1], 16;\n" :: "r"(saddr), "l"(g));
}
__device__ __forceinline__ void cp_commit() {
    asm volatile("cp.async.commit_group;\n" ::: "memory");
}
__device__ __forceinline__ void cp_wait1() {
    asm volatile("cp.async.wait_group 1;\n" ::: "memory");
}

__device__ __forceinline__ void mma_f16(
    float& c0, float& c1, float& c2, float& c3,
    uint32_t a0, uint32_t a1, uint32_t a2, uint32_t a3,
    uint32_t b0, uint32_t b1)
{
    asm volatile(
        "mma.sync.aligned.m16n8k16.row.col.f32.f16.f16.f32 "
        "{%0,%1,%2,%3},{%4,%5,%6,%7},{%8,%9},{%0,%1,%2,%3};"
        : "+f"(c0), "+f"(c1), "+f"(c2), "+f"(c3)
        : "r"(a0), "r"(a1), "r"(a2), "r"(a3), "r"(b0), "r"(b1));
}

#define LDMX4(r0, r1, r2, r3, addr) \
    asm volatile("ldmatrix.sync.aligned.m8n8.x4.shared.b16 {%0,%1,%2,%3}, [%4];" \
                 : "=r"(r0), "=r"(r1), "=r"(r2), "=r"(r3) : "r"(addr))
#define LDMX4T(r0, r1, r2, r3, addr) \
    asm volatile("ldmatrix.sync.aligned.m8n8.x4.trans.shared.b16 {%0,%1,%2,%3}, [%4];" \
                 : "=r"(r0), "=r"(r1), "=r"(r2), "=r"(r3) : "r"(addr))

__device__ __forceinline__ uint32_t packh2(float a, float b) {
    __half2 h = __floats2half2_rn(a, b);
    return *(uint32_t*)&h;
}

// ======================= rope table =======================
__global__ __launch_bounds__(256) void rope_table_kernel()
{
    int idx = blockIdx.x * 256 + threadIdx.x;     // SEQ*64
    int s = idx >> 6, d = idx & 63;
    float inv = __expf(-(float)(2 * d) / (float)HEAD_DIM * 9.210340371976184f); // ln(1e4)
    float fr = (float)s * inv;
    float c, sn;
    sincosf(fr, &sn, &c);
    g_rope[idx] = make_float2(c, sn);
}

// ======================= FP16 tensor GEMM =======================
#define ROWH  80
#define OPSTH (128 * ROWH)
#define GEMM_SMEM_BYTES (4 * OPSTH * 2)   // 81920 B

// ---- fused QKV + RoPE epilogue: grid (48, 32); j = bx>>4 ----
__global__ __launch_bounds__(256, 2) void gemm_qkv(
    const __half* __restrict__ A, const __half* __restrict__ BT3,
    const float* __restrict__ bq, const float* __restrict__ bk, const float* __restrict__ bv,
    const float* __restrict__ kw,
    __half* __restrict__ Qh, __half* __restrict__ Kh, __half* __restrict__ Vh)
{
    extern __shared__ __half smh[];
    const int tid  = threadIdx.x;
    const int lane = tid & 31;
    const int warp = tid >> 5;
    const int wm   = warp >> 2;
    const int wn   = warp & 3;
    const int g    = lane >> 2;
    const int t    = lane & 3;
    const int j    = blockIdx.x >> 4;          // 0=Q 1=K 2=V
    const int h    = blockIdx.x & 15;
    const int n0   = h * 128;
    const int m0   = blockIdx.y * 128;
    const __half* BT = BT3 + (size_t)j * HIDDEN * HIDDEN;
    const float* bias = (j == 0) ? bq : (j == 1) ? bk : bv;

    int crow[4], cseg[4];
#pragma unroll
    for (int jj = 0; jj < 4; jj++) {
        int cid = tid + jj * 256;
        crow[jj] = cid >> 3;
        cseg[jj] = (cid & 7) * 8;
    }

    float acc[4][4][4];
#pragma unroll
    for (int i = 0; i < 4; i++)
#pragma unroll
        for (int jj = 0; jj < 4; jj++)
#pragma unroll
            for (int e = 0; e < 4; e++) acc[i][jj][e] = 0.f;

    auto load_stage = [&](int s, int k0) {
        __half* as = smh + s * OPSTH;
        __half* bs = smh + 2 * OPSTH + s * OPSTH;
#pragma unroll
        for (int jj = 0; jj < 4; jj++) {
            uint32_t sa = (uint32_t)__cvta_generic_to_shared(&as[crow[jj] * ROWH + cseg[jj]]);
            cp_async16(sa, &A[(size_t)(m0 + crow[jj]) * HIDDEN + k0 + cseg[jj]]);
            uint32_t sb = (uint32_t)__cvta_generic_to_shared(&bs[crow[jj] * ROWH + cseg[jj]]);
            cp_async16(sb, &BT[(size_t)(n0 + crow[jj]) * HIDDEN + k0 + cseg[jj]]);
        }
        cp_commit();
    };

    const int niter = HIDDEN / 64;
    load_stage(0, 0);

    for (int it = 0; it < niter; it++) {
        const int buf = it & 1;
        if (it + 1 < niter) load_stage(buf ^ 1, (it + 1) * 64);
        else cp_commit();
        cp_wait1();
        __syncthreads();

        const __half* as = smh + buf * OPSTH;
        const __half* bs = smh + 2 * OPSTH + buf * OPSTH;

#pragma unroll
        for (int ks = 0; ks < 4; ks++) {
            const int ko = ks * 16 + 4 * t;
            uint2 alo[4], ahi[4], bfr[4];
#pragma unroll
            for (int mf = 0; mf < 4; mf++) {
                const __half* pa = as + (wm * 64 + mf * 16 + g) * ROWH + ko;
                alo[mf] = *(const uint2*)pa;
                ahi[mf] = *(const uint2*)(pa + 8 * ROWH);
            }
#pragma unroll
            for (int nf = 0; nf < 4; nf++) {
                const __half* pb = bs + (wn * 32 + nf * 8 + g) * ROWH + ko;
                bfr[nf] = *(const uint2*)pb;
            }
#pragma unroll
            for (int mf = 0; mf < 4; mf++)
#pragma unroll
                for (int nf = 0; nf < 4; nf++)
                    mma_f16(acc[mf][nf][0], acc[mf][nf][1], acc[mf][nf][2], acc[mf][nf][3],
                            alo[mf].x, ahi[mf].x, alo[mf].y, ahi[mf].y,
                            bfr[nf].x, bfr[nf].y);
        }
        __syncthreads();
    }

    const int b = m0 >> 11;

    if (j == 2) {
        // direct fp16 V store, head layout
        __half* Vb = Vh + (size_t)(b * NUM_HEADS + h) * SEQ * HEAD_DIM;
#pragma unroll
        for (int mf = 0; mf < 4; mf++) {
            int r0l = wm * 64 + mf * 16 + g;
            int s0 = (m0 + r0l) & (SEQ - 1);
            int s1 = s0 + 8;
#pragma unroll
            for (int nf = 0; nf < 4; nf++) {
                int col = wn * 32 + nf * 8 + 2 * t;
                float b0 = bias[n0 + col], b1 = bias[n0 + col + 1];
                *(uint32_t*)&Vb[(size_t)s0 * HEAD_DIM + col] =
                    packh2(acc[mf][nf][0] + b0, acc[mf][nf][1] + b1);
                *(uint32_t*)&Vb[(size_t)s1 * HEAD_DIM + col] =
                    packh2(acc[mf][nf][2] + b0, acc[mf][nf][3] + b1);
            }
        }
        return;
    }

    // ---- Q/K: stage through smem, apply RoPE, store fp16 ----
    float* buf = (float*)smh;   // [128][132]
#pragma unroll
    for (int mf = 0; mf < 4; mf++) {
        int r0l = wm * 64 + mf * 16 + g;
#pragma unroll
        for (int nf = 0; nf < 4; nf++) {
            int col = wn * 32 + nf * 8 + 2 * t;
            float b0 = bias[n0 + col], b1 = bias[n0 + col + 1];
            buf[r0l * 132 + col]           = acc[mf][nf][0] + b0;
            buf[r0l * 132 + col + 1]       = acc[mf][nf][1] + b1;
            buf[(r0l + 8) * 132 + col]     = acc[mf][nf][2] + b0;
            buf[(r0l + 8) * 132 + col + 1] = acc[mf][nf][3] + b1;
        }
    }
    __syncthreads();

    const float scale = (j == 0) ? kw[h] * 0.08838834764831845f : 1.0f;
    __half* dst = ((j == 0) ? Qh : Kh) + (size_t)(b * NUM_HEADS + h) * SEQ * HEAD_DIM;

#pragma unroll
    for (int it2 = 0; it2 < 8; it2++) {
        int idx = tid + it2 * 256;        // 2048 = 128 rows x 16 d-groups
        int row = idx >> 4;
        int dg  = (idx & 15) * 4;         // d = dg..dg+3 in [0,64)
        int s   = (m0 + row) & (SEQ - 1);
        float4 f1 = *(float4*)&buf[row * 132 + dg];
        float4 f2 = *(float4*)&buf[row * 132 + 64 + dg];
        float2 t0 = g_rope[s * 64 + dg];
        float2 t1 = g_rope[s * 64 + dg + 1];
        float2 t2 = g_rope[s * 64 + dg + 2];
        float2 t3 = g_rope[s * 64 + dg + 3];
        uint2 lo, hi;
        lo.x = packh2((f1.x * t0.x - f2.x * t0.y) * scale, (f1.y * t1.x - f2.y * t1.y) * scale);
        lo.y = packh2((f1.z * t2.x - f2.z * t2.y) * scale, (f1.w * t3.x - f2.w * t3.y) * scale);
        hi.x = packh2((f1.x * t0.y + f2.x * t0.x) * scale, (f1.y * t1.y + f2.y * t1.x) * scale);
        hi.y = packh2((f1.z * t2.y + f2.z * t2.x) * scale, (f1.w * t3.y + f2.w * t3.x) * scale);
        *(uint2*)&dst[(size_t)s * HEAD_DIM + dg]      = lo;
        *(uint2*)&dst[(size_t)s * HEAD_DIM + dg + 64] = hi;
    }
}

// ---- generic GEMM (O projection) ----
__global__ __launch_bounds__(256, 2) void gemm_f16(
    const __half* __restrict__ A, const __half* __restrict__ BT,
    const float* __restrict__ bias, float* __restrict__ C)
{
    extern __shared__ __half smh[];
    const int tid  = threadIdx.x;
    const int lane = tid & 31;
    const int warp = tid >> 5;
    const int wm   = warp >> 2;
    const int wn   = warp & 3;
    const int g    = lane >> 2;
    const int t    = lane & 3;
    const int m0   = blockIdx.y * 128;
    const int n0   = blockIdx.x * 128;

    int crow[4], cseg[4];
#pragma unroll
    for (int jj = 0; jj < 4; jj++) {
        int cid = tid + jj * 256;
        crow[jj] = cid >> 3;
        cseg[jj] = (cid & 7) * 8;
    }

    float acc[4][4][4];
#pragma unroll
    for (int i = 0; i < 4; i++)
#pragma unroll
        for (int jj = 0; jj < 4; jj++)
#pragma unroll
            for (int e = 0; e < 4; e++) acc[i][jj][e] = 0.f;

    auto load_stage = [&](int s, int k0) {
        __half* as = smh + s * OPSTH;
        __half* bs = smh + 2 * OPSTH + s * OPSTH;
#pragma unroll
        for (int jj = 0; jj < 4; jj++) {
            uint32_t sa = (uint32_t)__cvta_generic_to_shared(&as[crow[jj] * ROWH + cseg[jj]]);
            cp_async16(sa, &A[(size_t)(m0 + crow[jj]) * HIDDEN + k0 + cseg[jj]]);
            uint32_t sb = (uint32_t)__cvta_generic_to_shared(&bs[crow[jj] * ROWH + cseg[jj]]);
            cp_async16(sb, &BT[(size_t)(n0 + crow[jj]) * HIDDEN + k0 + cseg[jj]]);
        }
        cp_commit();
    };

    const int niter = HIDDEN / 64;
    load_stage(0, 0);

    for (int it = 0; it < niter; it++) {
        const int buf = it & 1;
        if (it + 1 < niter) load_stage(buf ^ 1, (it + 1) * 64);
        else cp_commit();
        cp_wait1();
        __syncthreads();

        const __half* as = smh + buf * OPSTH;
        const __half* bs = smh + 2 * OPSTH + buf * OPSTH;

#pragma unroll
        for (int ks = 0; ks < 4; ks++) {
            const int ko = ks * 16 + 4 * t;
            uint2 alo[4], ahi[4], bfr[4];
#pragma unroll
            for (int mf = 0; mf < 4; mf++) {
                const __half* pa = as + (wm * 64 + mf * 16 + g) * ROWH + ko;
                alo[mf] = *(const uint2*)pa;
                ahi[mf] = *(const uint2*)(pa + 8 * ROWH);
            }
#pragma unroll
            for (int nf = 0; nf < 4; nf++) {
                const __half* pb = bs + (wn * 32 + nf * 8 + g) * ROWH + ko;
                bfr[nf] = *(const uint2*)pb;
            }
#pragma unroll
            for (int mf = 0; mf < 4; mf++)
#pragma unroll
                for (int nf = 0; nf < 4; nf++)
                    mma_f16(acc[mf][nf][0], acc[mf][nf][1], acc[mf][nf][2], acc[mf][nf][3],
                            alo[mf].x, ahi[mf].x, alo[mf].y, ahi[mf].y,
                            bfr[nf].x, bfr[nf].y);
        }
        __syncthreads();
    }

#pragma unroll
    for (int mf = 0; mf < 4; mf++) {
        int row0 = m0 + wm * 64 + mf * 16 + g;
#pragma unroll
        for (int nf = 0; nf < 4; nf++) {
            int col = n0 + wn * 32 + nf * 8 + 2 * t;
            float b0 = bias[col], b1 = bias[col + 1];
            *(float2*)&C[(size_t)row0 * HIDDEN + col] =
                make_float2(acc[mf][nf][0] + b0, acc[mf][nf][1] + b1);
            *(float2*)&C[(size_t)(row0 + 8) * HIDDEN + col] =
                make_float2(acc[mf][nf][2] + b0, acc[mf][nf][3] + b1);
        }
    }
}

// ======================= prep kernels =======================
__global__ __launch_bounds__(256) void convert_perm_kernel(
    const float* __restrict__ in, __half* __restrict__ out)
{
    int i = (blockIdx.x * 256 + threadIdx.x) * 16;
    float4 u0 = *(const float4*)&in[i];
    float4 u1 = *(const float4*)&in[i + 4];
    float4 u2 = *(const float4*)&in[i + 8];
    float4 u3 = *(const float4*)&in[i + 12];
    __half2 h[8];
    h[0] = __floats2half2_rn(u0.x, u0.y);
    h[1] = __floats2half2_rn(u2.x, u2.y);
    h[2] = __floats2half2_rn(u0.z, u0.w);
    h[3] = __floats2half2_rn(u2.z, u2.w);
    h[4] = __floats2half2_rn(u1.x, u1.y);
    h[5] = __floats2half2_rn(u3.x, u3.y);
    h[6] = __floats2half2_rn(u1.z, u1.w);
    h[7] = __floats2half2_rn(u3.z, u3.w);
    *(uint4*)&out[i]     = *(uint4*)&h[0];
    *(uint4*)&out[i + 8] = *(uint4*)&h[4];
}

// all 4 weights in one launch; blockIdx.z selects
__global__ __launch_bounds__(256) void transpose_convert4_kernel(
    const float* __restrict__ W0, const float* __restrict__ W1,
    const float* __restrict__ W2, const float* __restrict__ W3,
    __half* __restrict__ WT)
{
    const int z = blockIdx.z;
    const float* W = (z == 0) ? W0 : (z == 1) ? W1 : (z == 2) ? W2 : W3;
    __half* dst = WT + (size_t)z * HIDDEN * HIDDEN;

    __shared__ float tle[32][33];
    int x  = blockIdx.x * 32 + threadIdx.x;
    int y0 = blockIdx.y * 32 + threadIdx.y;
#pragma unroll
    for (int i = 0; i < 4; i++)
        tle[threadIdx.y + i * 8][threadIdx.x] = W[(size_t)(y0 + i * 8) * HIDDEN + x];
    __syncthreads();
    int xk = blockIdx.y * 32 + threadIdx.x;
    int q  = xk & 15;
    int newk = (xk & ~15) + 4 * ((q & 7) >> 1) + 2 * (q >> 3) + (q & 1);
    int yn = blockIdx.x * 32 + threadIdx.y;
#pragma unroll
    for (int i = 0; i < 4; i++)
        dst[(size_t)(yn + i * 8) * HIDDEN + newk] =
            __float2half_rn(tle[threadIdx.x][threadIdx.y + i * 8]);
}

// ======================= Tensor-core sliding-window attention =======================
// 256 threads (8 warps), 128-query tile, 64-key chunks.
#define SQH 136
#define ATTN_SMEM_BYTES ((128 + 64 + 64) * SQH * 2)   // 69632

__global__ __launch_bounds__(256) void swattn_mma(
    const __half* __restrict__ Qh, const __half* __restrict__ Kh,
    const __half* __restrict__ Vh, __half* __restrict__ AOh)
{
    extern __shared__ __half smh[];
    __half* Qs = smh;                   // 128 x SQH
    __half* Ks = smh + 128 * SQH;       // 64 x SQH
    __half* Vs = smh + 192 * SQH;       // 64 x SQH

    const int tid  = threadIdx.x;
    const int w    = tid >> 5;
    const int lane = tid & 31;
    const int g    = lane >> 2;
    const int t    = lane & 3;
    const int bh   = blockIdx.y;
    const int q0   = blockIdx.x * 128;
    const int qr   = w * 16;
    const int qmin = q0 + qr;
    const int qmax = qmin + 15;

    const uint32_t qs_b = smem_u32(Qs);
    const uint32_t ks_b = smem_u32(Ks);
    const uint32_t vs_b = smem_u32(Vs);

    const int l7 = lane & 7;
    const uint32_t a_addr = qs_b +
        (uint32_t)(((qr + l7 + (lane & 8)) * SQH + ((lane & 16) ? 8 : 0)) * 2);
    const int k_rowc = ((lane >> 4) * 8 + l7);
    const int k_colo = (lane & 8) ? 8 : 0;
    const int v_rowc = (((lane >> 3) & 1) * 8 + l7);
    const int v_colc = (lane >> 4) * 8;

    // load Q tile (128 rows)
    const __half* Qg = Qh + (size_t)(bh * SEQ + q0) * HEAD_DIM;
#pragma unroll
    for (int it = 0; it < 8; it++) {
        int lin = tid + it * 256;
        int row = lin >> 4, seg = (lin & 15) * 8;
        *(uint4*)&Qs[row * SQH + seg] = *(const uint4*)&Qg[row * HEAD_DIM + seg];
    }

    float m0 = -1e30f, m1 = -1e30f, l0 = 0.f, l1 = 0.f;
    float oacc[16][4];
#pragma unroll
    for (int dn = 0; dn < 16; dn++)
#pragma unroll
        for (int e = 0; e < 4; e++) oacc[dn][e] = 0.f;

    const __half* Kg = Kh + (size_t)bh * SEQ * HEAD_DIM;
    const __half* Vg = Vh + (size_t)bh * SEQ * HEAD_DIM;

    int cs = q0 - WINDOW; if (cs < 0) cs = 0;
    const int kend = q0 + 64;

    for (int k0 = cs; k0 <= kend; k0 += 64) {
        __syncthreads();
#pragma unroll
        for (int it = 0; it < 4; it++) {
            int lin = tid + it * 256;
            int row = lin >> 4, seg = (lin & 15) * 8;
            *(uint4*)&Ks[row * SQH + seg] = *(const uint4*)&Kg[(size_t)(k0 + row) * HEAD_DIM + seg];
            *(uint4*)&Vs[row * SQH + seg] = *(const uint4*)&Vg[(size_t)(k0 + row) * HEAD_DIM + seg];
        }
        __syncthreads();

        const bool skip = (k0 > qmax) || (k0 + 63 < qmin - WINDOW);
        if (skip) continue;
        const bool needMask =
            (k0 + 63 >= qmin && k0 <= qmax) ||
            (k0 + 63 >= qmin - WINDOW && k0 <= qmax - WINDOW);

        // ---- scores: 16q x 64k over d=128 ----
        float sc[8][4];
#pragma unroll
        for (int kg = 0; kg < 8; kg++)
#pragma unroll
            for (int e = 0; e < 4; e++) sc[kg][e] = 0.f;

#pragma unroll
        for (int kk = 0; kk < 8; kk++) {
            uint32_t a0, a1, a2, a3;
            LDMX4(a0, a1, a2, a3, a_addr + kk * 32);
#pragma unroll
            for (int p = 0; p < 4; p++) {
                uint32_t b0, b1, b2, b3;
                uint32_t kaddr = ks_b +
                    (uint32_t)((((k_rowc + p * 16) * SQH) + kk * 16 + k_colo) * 2);
                LDMX4(b0, b1, b2, b3, kaddr);
                mma_f16(sc[2*p][0], sc[2*p][1], sc[2*p][2], sc[2*p][3],
                        a0, a1, a2, a3, b0, b1);
                mma_f16(sc[2*p+1][0], sc[2*p+1][1], sc[2*p+1][2], sc[2*p+1][3],
                        a0, a1, a2, a3, b2, b3);
            }
        }

        if (needMask) {
            const int qga = qmin + g;
            const int qgb = qga + 8;
#pragma unroll
            for (int kg = 0; kg < 8; kg++) {
                int key = k0 + kg * 8 + 2 * t;
                if (key     > qga || key     < qga - WINDOW) sc[kg][0] = -1e30f;
                if (key + 1 > qga || key + 1 < qga - WINDOW) sc[kg][1] = -1e30f;
                if (key     > qgb || key     < qgb - WINDOW) sc[kg][2] = -1e30f;
                if (key + 1 > qgb || key + 1 < qgb - WINDOW) sc[kg][3] = -1e30f;
            }
        }

        // ---- online softmax ----
        float mx0 = -1e30f, mx1 = -1e30f;
#pragma unroll
        for (int kg = 0; kg < 8; kg++) {
            mx0 = fmaxf(mx0, fmaxf(sc[kg][0], sc[kg][1]));
            mx1 = fmaxf(mx1, fmaxf(sc[kg][2], sc[kg][3]));
        }
        mx0 = fmaxf(mx0, __shfl_xor_sync(0xffffffffu, mx0, 1));
        mx0 = fmaxf(mx0, __shfl_xor_sync(0xffffffffu, mx0, 2));
        mx1 = fmaxf(mx1, __shfl_xor_sync(0xffffffffu, mx1, 1));
        mx1 = fmaxf(mx1, __shfl_xor_sync(0xffffffffu, mx1, 2));

        float nm0 = fmaxf(m0, mx0), nm1 = fmaxf(m1, mx1);
        float rs0 = __expf(m0 - nm0), rs1 = __expf(m1 - nm1);

        float s0 = 0.f, s1 = 0.f;
        uint32_t ph[8][2];
#pragma unroll
        for (int kg = 0; kg < 8; kg++) {
            float p0 = __expf(sc[kg][0] - nm0);
            float p1 = __expf(sc[kg][1] - nm0);
            float p2 = __expf(sc[kg][2] - nm1);
            float p3 = __expf(sc[kg][3] - nm1);
            s0 += p0 + p1;
            s1 += p2 + p3;
            ph[kg][0] = packh2(p0, p1);
            ph[kg][1] = packh2(p2, p3);
        }
        s0 += __shfl_xor_sync(0xffffffffu, s0, 1);
        s0 += __shfl_xor_sync(0xffffffffu, s0, 2);
        s1 += __shfl_xor_sync(0xffffffffu, s1, 1);
        s1 += __shfl_xor_sync(0xffffffffu, s1, 2);

        l0 = l0 * rs0 + s0;
        l1 = l1 * rs1 + s1;
        m0 = nm0; m1 = nm1;

#pragma unroll
        for (int dn = 0; dn < 16; dn++) {
            oacc[dn][0] *= rs0; oacc[dn][1] *= rs0;
            oacc[dn][2] *= rs1; oacc[dn][3] *= rs1;
        }

        // ---- PV ----
#pragma unroll
        for (int ck = 0; ck < 4; ck++) {
            uint32_t pa0 = ph[2*ck][0], pa1 = ph[2*ck][1];
            uint32_t pa2 = ph[2*ck+1][0], pa3 = ph[2*ck+1][1];
#pragma unroll
            for (int dp = 0; dp < 8; dp++) {
                uint32_t v0, v1, v2, v3;
                uint32_t vaddr = vs_b +
                    (uint32_t)((((v_rowc + ck * 16) * SQH) + dp * 16 + v_colc) * 2);
                LDMX4T(v0, v1, v2, v3, vaddr);
                mma_f16(oacc[2*dp][0], oacc[2*dp][1], oacc[2*dp][2], oacc[2*dp][3],
                        pa0, pa1, pa2, pa3, v0, v1);
                mma_f16(oacc[2*dp+1][0], oacc[2*dp+1][1], oacc[2*dp+1][2], oacc[2*dp+1][3],
                        pa0, pa1, pa2, pa3, v2, v3);
            }
        }
    }

    // ---- epilogue: normalize + fp16 k-permuted store ----
    float inv0 = 1.f / l0, inv1 = 1.f / l1;
    const int b = bh >> 4, h = bh & (NUM_HEADS - 1);
    size_t rowa = (size_t)(b * SEQ + q0 + qr + g) * HIDDEN;
    size_t rowb = rowa + (size_t)8 * HIDDEN;
#pragma unroll
    for (int dn = 0; dn < 16; dn++) {
        int a = dn & 1;
        int col = h * 128 + (dn >> 1) * 16 + 4 * t + 2 * a;
        *(uint32_t*)&AOh[rowa + col] = packh2(oacc[dn][0] * inv0, oacc[dn][1] * inv0);
        *(uint32_t*)&AOh[rowb + col] = packh2(oacc[dn][2] * inv1, oacc[dn][3] * inv1);
    }
}

// ======================= launch =======================
extern "C" void kernel_launch(void* const* d_in, const int* in_sizes, int n_in,
                              void* d_out, int out_size)
{
    const float* x   = (const float*)d_in[0];
    const float* W_Q = (const float*)d_in[1];
    const float* b_Q = (const float*)d_in[2];
    const float* W_K = (const float*)d_in[3];
    const float* b_K = (const float*)d_in[4];
    const float* W_V = (const float*)d_in[5];
    const float* b_V = (const float*)d_in[6];
    const float* W_O = (const float*)d_in[7];
    const float* b_O = (const float*)d_in[8];
    const float* kw  = (const float*)d_in[9];

    __half *Qh, *Kh, *Vh, *Xh, *AOh, *WTh4;
    cudaGetSymbolAddress((void**)&Qh,   g_Qh);
    cudaGetSymbolAddress((void**)&Kh,   g_Kh);
    cudaGetSymbolAddress((void**)&Vh,   g_Vh);
    cudaGetSymbolAddress((void**)&Xh,   g_Xh);
    cudaGetSymbolAddress((void**)&AOh,  g_AOh);
    cudaGetSymbolAddress((void**)&WTh4, g_WTh4);

    cudaFuncSetAttribute(gemm_qkv,
                         cudaFuncAttributeMaxDynamicSharedMemorySize, GEMM_SMEM_BYTES);
    cudaFuncSetAttribute(gemm_f16,
                         cudaFuncAttributeMaxDynamicSharedMemorySize, GEMM_SMEM_BYTES);
    cudaFuncSetAttribute(swattn_mma,
                         cudaFuncAttributeMaxDynamicSharedMemorySize, ATTN_SMEM_BYTES);

    // 0. rope table + input conversion
    rope_table_kernel<<<SEQ * 64 / 256, 256>>>();
    convert_perm_kernel<<<M_ROWS * HIDDEN / (256 * 16), 256>>>(x, Xh);

    // 1. all 4 weight transposes, one launch
    dim3 tg(HIDDEN / 32, HIDDEN / 32, 4);
    dim3 tb(32, 8);
    transpose_convert4_kernel<<<tg, tb>>>(W_Q, W_K, W_V, W_O, WTh4);

    // 2. fused QKV GEMM + RoPE epilogue
    dim3 gq(48, M_ROWS / 128);
    gemm_qkv<<<gq, 256, GEMM_SMEM_BYTES>>>(Xh, WTh4, b_Q, b_K, b_V, kw, Qh, Kh, Vh);

    // 3. attention (128-query tiles)
    dim3 ga(SEQ / 128, BATCH * NUM_HEADS);
    swattn_mma<<<ga, 256, ATTN_SMEM_BYTES>>>(Qh, Kh, Vh, AOh);

    // 4. O projection
    dim3 go(HIDDEN / 128, M_ROWS / 128);
    gemm_f16<<<go, 256, GEMM_SMEM_BYTES>>>(AOh, WTh4 + (size_t)3 * HIDDEN * HIDDEN,
                                           b_O, (float*)d_out);
}

// round 8
// speedup vs baseline: 3.8263x; 1.0504x over previous
#include <cuda_runtime.h>
#include <cuda_fp16.h>
#include <math.h>
#include <stdint.h>

#define HIDDEN    2048
#define NUM_HEADS 16
#define HEAD_DIM  128
#define WINDOW    256
#define BATCH     2
#define SEQ       2048
#define M_ROWS    (BATCH * SEQ)        // 4096

// -------- scratch (static device buffers; no allocation allowed) --------
__device__ __half g_Qh[BATCH * NUM_HEADS * SEQ * HEAD_DIM];   // f16 post-rope, kw-scaled
__device__ __half g_Kh[BATCH * NUM_HEADS * SEQ * HEAD_DIM];   // f16 post-rope
__device__ __half g_Vh[BATCH * NUM_HEADS * SEQ * HEAD_DIM];
__device__ __half g_Xh[M_ROWS * HIDDEN];                       // x, fp16 (plain layout)
__device__ __half g_AOh[M_ROWS * HIDDEN];                      // attn out, fp16 (plain)
__device__ __half g_WTh4[4 * HIDDEN * HIDDEN];                 // W^T x4, fp16 (plain)
__device__ float2 g_rope[SEQ * 64];                            // (cos, sin) per (s, d-pair)

// ======================= helpers =======================
__device__ __forceinline__ uint32_t smem_u32(const void* p) {
    uint32_t a;
    asm("{ .reg .u64 t; cvta.to.shared.u64 t, %1; cvt.u32.u64 %0, t; }" : "=r"(a) : "l"(p));
    return a;
}
__device__ __forceinline__ void cp_async16(uint32_t saddr, const void* g) {
    asm volatile("cp.async.cg.shared.global [%0], [%1], 16;\n" :: "r"(saddr), "l"(g));
}
__device__ __forceinline__ void cp_commit() {
    asm volatile("cp.async.commit_group;\n" ::: "memory");
}
__device__ __forceinline__ void cp_wait1() {
    asm volatile("cp.async.wait_group 1;\n" ::: "memory");
}

__device__ __forceinline__ void mma_f16(
    float& c0, float& c1, float& c2, float& c3,
    uint32_t a0, uint32_t a1, uint32_t a2, uint32_t a3,
    uint32_t b0, uint32_t b1)
{
    asm volatile(
        "mma.sync.aligned.m16n8k16.row.col.f32.f16.f16.f32 "
        "{%0,%1,%2,%3},{%4,%5,%6,%7},{%8,%9},{%0,%1,%2,%3};"
        : "+f"(c0), "+f"(c1), "+f"(c2), "+f"(c3)
        : "r"(a0), "r"(a1), "r"(a2), "r"(a3), "r"(b0), "r"(b1));
}

#define LDMX4(r0, r1, r2, r3, addr) \
    asm volatile("ldmatrix.sync.aligned.m8n8.x4.shared.b16 {%0,%1,%2,%3}, [%4];" \
                 : "=r"(r0), "=r"(r1), "=r"(r2), "=r"(r3) : "r"(addr))
#define LDMX4T(r0, r1, r2, r3, addr) \
    asm volatile("ldmatrix.sync.aligned.m8n8.x4.trans.shared.b16 {%0,%1,%2,%3}, [%4];" \
                 : "=r"(r0), "=r"(r1), "=r"(r2), "=r"(r3) : "r"(addr))

__device__ __forceinline__ uint32_t packh2(float a, float b) {
    __half2 h = __floats2half2_rn(a, b);
    return *(uint32_t*)&h;
}

// ======================= rope table =======================
__global__ __launch_bounds__(256) void rope_table_kernel()
{
    int idx = blockIdx.x * 256 + threadIdx.x;     // SEQ*64
    int s = idx >> 6, d = idx & 63;
    float inv = __expf(-(float)(2 * d) / (float)HEAD_DIM * 9.210340371976184f); // ln(1e4)
    float fr = (float)s * inv;
    float c, sn;
    sincosf(fr, &sn, &c);
    g_rope[idx] = make_float2(c, sn);
}

// ======================= FP16 tensor GEMM (ldmatrix operand path) =======================
#define ROWH  72                         // smem row stride in halfs (144B; 36w ≡ 4 mod 32)
#define OPSTH (128 * ROWH)               // 9216 halfs per operand per stage
#define GEMM_SMEM_BYTES (4 * OPSTH * 2)  // 73728 B

// inner mainloop shared by both GEMMs (acc[4][4][4] must be in scope)
#define GEMM_MAINLOOP(A_, BT_)                                                         \
    int crow[4], cseg[4];                                                              \
    _Pragma("unroll")                                                                  \
    for (int jj = 0; jj < 4; jj++) {                                                   \
        int cid = tid + jj * 256;                                                      \
        crow[jj] = cid >> 3;                                                           \
        cseg[jj] = (cid & 7) * 8;                                                      \
    }                                                                                  \
    const uint32_t sb0 = smem_u32(smh);                                                \
    const int l7 = lane & 7;                                                           \
    const uint32_t a_base = sb0 +                                                      \
        (uint32_t)(((wm * 64 + l7 + (lane & 8)) * ROWH + ((lane & 16) ? 8 : 0)) * 2);  \
    const uint32_t b_base = sb0 + 2 * OPSTH * 2 +                                      \
        (uint32_t)(((wn * 32 + (lane >> 4) * 8 + l7) * ROWH + ((lane & 8) ? 8 : 0)) * 2); \
    auto load_stage = [&](int s, int k0) {                                             \
        __half* as = smh + s * OPSTH;                                                  \
        __half* bs = smh + 2 * OPSTH + s * OPSTH;                                      \
        _Pragma("unroll")                                                              \
        for (int jj = 0; jj < 4; jj++) {                                               \
            uint32_t sa = (uint32_t)__cvta_generic_to_shared(&as[crow[jj] * ROWH + cseg[jj]]); \
            cp_async16(sa, &A_[(size_t)(m0 + crow[jj]) * HIDDEN + k0 + cseg[jj]]);     \
            uint32_t sb = (uint32_t)__cvta_generic_to_shared(&bs[crow[jj] * ROWH + cseg[jj]]); \
            cp_async16(sb, &BT_[(size_t)(n0 + crow[jj]) * HIDDEN + k0 + cseg[jj]]);    \
        }                                                                              \
        cp_commit();                                                                   \
    };                                                                                 \
    const int niter = HIDDEN / 64;                                                     \
    load_stage(0, 0);                                                                  \
    for (int it = 0; it < niter; it++) {                                               \
        const int buf = it & 1;                                                        \
        if (it + 1 < niter) load_stage(buf ^ 1, (it + 1) * 64);                        \
        else cp_commit();                                                              \
        cp_wait1();                                                                    \
        __syncthreads();                                                               \
        const uint32_t aS = a_base + (uint32_t)(buf * OPSTH * 2);                      \
        const uint32_t bS = b_base + (uint32_t)(buf * OPSTH * 2);                      \
        _Pragma("unroll")                                                              \
        for (int ks = 0; ks < 4; ks++) {                                               \
            uint32_t af[4][4], bf[2][4];                                               \
            _Pragma("unroll")                                                          \
            for (int mf = 0; mf < 4; mf++)                                             \
                LDMX4(af[mf][0], af[mf][1], af[mf][2], af[mf][3],                      \
                      aS + (uint32_t)(mf * 16 * ROWH * 2 + ks * 32));                  \
            _Pragma("unroll")                                                          \
            for (int np = 0; np < 2; np++)                                             \
                LDMX4(bf[np][0], bf[np][1], bf[np][2], bf[np][3],                      \
                      bS + (uint32_t)(np * 16 * ROWH * 2 + ks * 32));                  \
            _Pragma("unroll")                                                          \
            for (int mf = 0; mf < 4; mf++)                                             \
                _Pragma("unroll")                                                      \
                for (int np = 0; np < 2; np++) {                                       \
                    mma_f16(acc[mf][2*np][0], acc[mf][2*np][1],                        \
                            acc[mf][2*np][2], acc[mf][2*np][3],                        \
                            af[mf][0], af[mf][1], af[mf][2], af[mf][3],                \
                            bf[np][0], bf[np][1]);                                     \
                    mma_f16(acc[mf][2*np+1][0], acc[mf][2*np+1][1],                    \
                            acc[mf][2*np+1][2], acc[mf][2*np+1][3],                    \
                            af[mf][0], af[mf][1], af[mf][2], af[mf][3],                \
                            bf[np][2], bf[np][3]);                                     \
                }                                                                      \
        }                                                                              \
        __syncthreads();                                                               \
    }

// ---- fused QKV + RoPE epilogue: grid (48, 32); j = bx>>4 ----
__global__ __launch_bounds__(256, 2) void gemm_qkv(
    const __half* __restrict__ A, const __half* __restrict__ BT3,
    const float* __restrict__ bq, const float* __restrict__ bk, const float* __restrict__ bv,
    const float* __restrict__ kw,
    __half* __restrict__ Qh, __half* __restrict__ Kh, __half* __restrict__ Vh)
{
    extern __shared__ __half smh[];
    const int tid  = threadIdx.x;
    const int lane = tid & 31;
    const int warp = tid >> 5;
    const int wm   = warp >> 2;
    const int wn   = warp & 3;
    const int g    = lane >> 2;
    const int t    = lane & 3;
    const int j    = blockIdx.x >> 4;          // 0=Q 1=K 2=V
    const int h    = blockIdx.x & 15;
    const int n0   = h * 128;
    const int m0   = blockIdx.y * 128;
    const __half* BT = BT3 + (size_t)j * HIDDEN * HIDDEN;
    const float* bias = (j == 0) ? bq : (j == 1) ? bk : bv;

    float acc[4][4][4];
#pragma unroll
    for (int i = 0; i < 4; i++)
#pragma unroll
        for (int jj = 0; jj < 4; jj++)
#pragma unroll
            for (int e = 0; e < 4; e++) acc[i][jj][e] = 0.f;

    GEMM_MAINLOOP(A, BT)

    const int b = m0 >> 11;

    if (j == 2) {
        __half* Vb = Vh + (size_t)(b * NUM_HEADS + h) * SEQ * HEAD_DIM;
#pragma unroll
        for (int mf = 0; mf < 4; mf++) {
            int r0l = wm * 64 + mf * 16 + g;
            int s0 = (m0 + r0l) & (SEQ - 1);
            int s1 = s0 + 8;
#pragma unroll
            for (int nf = 0; nf < 4; nf++) {
                int col = wn * 32 + nf * 8 + 2 * t;
                float b0 = bias[n0 + col], b1 = bias[n0 + col + 1];
                *(uint32_t*)&Vb[(size_t)s0 * HEAD_DIM + col] =
                    packh2(acc[mf][nf][0] + b0, acc[mf][nf][1] + b1);
                *(uint32_t*)&Vb[(size_t)s1 * HEAD_DIM + col] =
                    packh2(acc[mf][nf][2] + b0, acc[mf][nf][3] + b1);
            }
        }
        return;
    }

    // ---- Q/K: stage through smem, apply RoPE, store fp16 ----
    float* buf = (float*)smh;   // [128][132]
#pragma unroll
    for (int mf = 0; mf < 4; mf++) {
        int r0l = wm * 64 + mf * 16 + g;
#pragma unroll
        for (int nf = 0; nf < 4; nf++) {
            int col = wn * 32 + nf * 8 + 2 * t;
            float b0 = bias[n0 + col], b1 = bias[n0 + col + 1];
            buf[r0l * 132 + col]           = acc[mf][nf][0] + b0;
            buf[r0l * 132 + col + 1]       = acc[mf][nf][1] + b1;
            buf[(r0l + 8) * 132 + col]     = acc[mf][nf][2] + b0;
            buf[(r0l + 8) * 132 + col + 1] = acc[mf][nf][3] + b1;
        }
    }
    __syncthreads();

    const float scale = (j == 0) ? kw[h] * 0.08838834764831845f : 1.0f;
    __half* dst = ((j == 0) ? Qh : Kh) + (size_t)(b * NUM_HEADS + h) * SEQ * HEAD_DIM;

#pragma unroll
    for (int it2 = 0; it2 < 8; it2++) {
        int idx = tid + it2 * 256;
        int row = idx >> 4;
        int dg  = (idx & 15) * 4;
        int s   = (m0 + row) & (SEQ - 1);
        float4 f1 = *(float4*)&buf[row * 132 + dg];
        float4 f2 = *(float4*)&buf[row * 132 + 64 + dg];
        float2 t0 = g_rope[s * 64 + dg];
        float2 t1 = g_rope[s * 64 + dg + 1];
        float2 t2 = g_rope[s * 64 + dg + 2];
        float2 t3 = g_rope[s * 64 + dg + 3];
        uint2 lo, hi;
        lo.x = packh2((f1.x * t0.x - f2.x * t0.y) * scale, (f1.y * t1.x - f2.y * t1.y) * scale);
        lo.y = packh2((f1.z * t2.x - f2.z * t2.y) * scale, (f1.w * t3.x - f2.w * t3.y) * scale);
        hi.x = packh2((f1.x * t0.y + f2.x * t0.x) * scale, (f1.y * t1.y + f2.y * t1.x) * scale);
        hi.y = packh2((f1.z * t2.y + f2.z * t2.x) * scale, (f1.w * t3.y + f2.w * t3.x) * scale);
        *(uint2*)&dst[(size_t)s * HEAD_DIM + dg]      = lo;
        *(uint2*)&dst[(size_t)s * HEAD_DIM + dg + 64] = hi;
    }
}

// ---- generic GEMM (O projection) ----
__global__ __launch_bounds__(256, 2) void gemm_f16(
    const __half* __restrict__ A, const __half* __restrict__ BT,
    const float* __restrict__ bias, float* __restrict__ C)
{
    extern __shared__ __half smh[];
    const int tid  = threadIdx.x;
    const int lane = tid & 31;
    const int warp = tid >> 5;
    const int wm   = warp >> 2;
    const int wn   = warp & 3;
    const int g    = lane >> 2;
    const int t    = lane & 3;
    const int m0   = blockIdx.y * 128;
    const int n0   = blockIdx.x * 128;

    float acc[4][4][4];
#pragma unroll
    for (int i = 0; i < 4; i++)
#pragma unroll
        for (int jj = 0; jj < 4; jj++)
#pragma unroll
            for (int e = 0; e < 4; e++) acc[i][jj][e] = 0.f;

    GEMM_MAINLOOP(A, BT)

#pragma unroll
    for (int mf = 0; mf < 4; mf++) {
        int row0 = m0 + wm * 64 + mf * 16 + g;
#pragma unroll
        for (int nf = 0; nf < 4; nf++) {
            int col = n0 + wn * 32 + nf * 8 + 2 * t;
            float b0 = bias[col], b1 = bias[col + 1];
            *(float2*)&C[(size_t)row0 * HIDDEN + col] =
                make_float2(acc[mf][nf][0] + b0, acc[mf][nf][1] + b1);
            *(float2*)&C[(size_t)(row0 + 8) * HIDDEN + col] =
                make_float2(acc[mf][nf][2] + b0, acc[mf][nf][3] + b1);
        }
    }
}

// ======================= prep kernels =======================
__global__ __launch_bounds__(256) void convert_half_kernel(
    const float* __restrict__ in, __half* __restrict__ out)
{
    int i = (blockIdx.x * 256 + threadIdx.x) * 8;
    float4 u0 = *(const float4*)&in[i];
    float4 u1 = *(const float4*)&in[i + 4];
    __half2 h[4];
    h[0] = __floats2half2_rn(u0.x, u0.y);
    h[1] = __floats2half2_rn(u0.z, u0.w);
    h[2] = __floats2half2_rn(u1.x, u1.y);
    h[3] = __floats2half2_rn(u1.z, u1.w);
    *(uint4*)&out[i] = *(uint4*)&h[0];
}

__global__ __launch_bounds__(256) void transpose_convert4_kernel(
    const float* __restrict__ W0, const float* __restrict__ W1,
    const float* __restrict__ W2, const float* __restrict__ W3,
    __half* __restrict__ WT)
{
    const int z = blockIdx.z;
    const float* W = (z == 0) ? W0 : (z == 1) ? W1 : (z == 2) ? W2 : W3;
    __half* dst = WT + (size_t)z * HIDDEN * HIDDEN;

    __shared__ float tle[32][33];
    int x  = blockIdx.x * 32 + threadIdx.x;
    int y0 = blockIdx.y * 32 + threadIdx.y;
#pragma unroll
    for (int i = 0; i < 4; i++)
        tle[threadIdx.y + i * 8][threadIdx.x] = W[(size_t)(y0 + i * 8) * HIDDEN + x];
    __syncthreads();
    int xk = blockIdx.y * 32 + threadIdx.x;
    int yn = blockIdx.x * 32 + threadIdx.y;
#pragma unroll
    for (int i = 0; i < 4; i++)
        dst[(size_t)(yn + i * 8) * HIDDEN + xk] =
            __float2half_rn(tle[threadIdx.x][threadIdx.y + i * 8]);
}

// ======================= Tensor-core sliding-window attention =======================
#define SQH 136
#define ATTN_SMEM_BYTES ((128 + 64 + 64) * SQH * 2)   // 69632

__global__ __launch_bounds__(256) void swattn_mma(
    const __half* __restrict__ Qh, const __half* __restrict__ Kh,
    const __half* __restrict__ Vh, __half* __restrict__ AOh)
{
    extern __shared__ __half smh[];
    __half* Qs = smh;                   // 128 x SQH
    __half* Ks = smh + 128 * SQH;       // 64 x SQH
    __half* Vs = smh + 192 * SQH;       // 64 x SQH

    const int tid  = threadIdx.x;
    const int w    = tid >> 5;
    const int lane = tid & 31;
    const int g    = lane >> 2;
    const int t    = lane & 3;
    const int bh   = blockIdx.y;
    const int q0   = blockIdx.x * 128;
    const int qr   = w * 16;
    const int qmin = q0 + qr;
    const int qmax = qmin + 15;

    const uint32_t qs_b = smem_u32(Qs);
    const uint32_t ks_b = smem_u32(Ks);
    const uint32_t vs_b = smem_u32(Vs);

    const int l7 = lane & 7;
    const uint32_t a_addr = qs_b +
        (uint32_t)(((qr + l7 + (lane & 8)) * SQH + ((lane & 16) ? 8 : 0)) * 2);
    const int k_rowc = ((lane >> 4) * 8 + l7);
    const int k_colo = (lane & 8) ? 8 : 0;
    const int v_rowc = (((lane >> 3) & 1) * 8 + l7);
    const int v_colc = (lane >> 4) * 8;

    const __half* Qg = Qh + (size_t)(bh * SEQ + q0) * HEAD_DIM;
#pragma unroll
    for (int it = 0; it < 8; it++) {
        int lin = tid + it * 256;
        int row = lin >> 4, seg = (lin & 15) * 8;
        *(uint4*)&Qs[row * SQH + seg] = *(const uint4*)&Qg[row * HEAD_DIM + seg];
    }

    float m0 = -1e30f, m1 = -1e30f, l0 = 0.f, l1 = 0.f;
    float oacc[16][4];
#pragma unroll
    for (int dn = 0; dn < 16; dn++)
#pragma unroll
        for (int e = 0; e < 4; e++) oacc[dn][e] = 0.f;

    const __half* Kg = Kh + (size_t)bh * SEQ * HEAD_DIM;
    const __half* Vg = Vh + (size_t)bh * SEQ * HEAD_DIM;

    int cs = q0 - WINDOW; if (cs < 0) cs = 0;
    const int kend = q0 + 64;

    for (int k0 = cs; k0 <= kend; k0 += 64) {
        __syncthreads();
#pragma unroll
        for (int it = 0; it < 4; it++) {
            int lin = tid + it * 256;
            int row = lin >> 4, seg = (lin & 15) * 8;
            *(uint4*)&Ks[row * SQH + seg] = *(const uint4*)&Kg[(size_t)(k0 + row) * HEAD_DIM + seg];
            *(uint4*)&Vs[row * SQH + seg] = *(const uint4*)&Vg[(size_t)(k0 + row) * HEAD_DIM + seg];
        }
        __syncthreads();

        const bool skip = (k0 > qmax) || (k0 + 63 < qmin - WINDOW);
        if (skip) continue;
        const bool needMask =
            (k0 + 63 >= qmin && k0 <= qmax) ||
            (k0 + 63 >= qmin - WINDOW && k0 <= qmax - WINDOW);

        float sc[8][4];
#pragma unroll
        for (int kg = 0; kg < 8; kg++)
#pragma unroll
            for (int e = 0; e < 4; e++) sc[kg][e] = 0.f;

#pragma unroll
        for (int kk = 0; kk < 8; kk++) {
            uint32_t a0, a1, a2, a3;
            LDMX4(a0, a1, a2, a3, a_addr + kk * 32);
#pragma unroll
            for (int p = 0; p < 4; p++) {
                uint32_t b0, b1, b2, b3;
                uint32_t kaddr = ks_b +
                    (uint32_t)((((k_rowc + p * 16) * SQH) + kk * 16 + k_colo) * 2);
                LDMX4(b0, b1, b2, b3, kaddr);
                mma_f16(sc[2*p][0], sc[2*p][1], sc[2*p][2], sc[2*p][3],
                        a0, a1, a2, a3, b0, b1);
                mma_f16(sc[2*p+1][0], sc[2*p+1][1], sc[2*p+1][2], sc[2*p+1][3],
                        a0, a1, a2, a3, b2, b3);
            }
        }

        if (needMask) {
            const int qga = qmin + g;
            const int qgb = qga + 8;
#pragma unroll
            for (int kg = 0; kg < 8; kg++) {
                int key = k0 + kg * 8 + 2 * t;
                if (key     > qga || key     < qga - WINDOW) sc[kg][0] = -1e30f;
                if (key + 1 > qga || key + 1 < qga - WINDOW) sc[kg][1] = -1e30f;
                if (key     > qgb || key     < qgb - WINDOW) sc[kg][2] = -1e30f;
                if (key + 1 > qgb || key + 1 < qgb - WINDOW) sc[kg][3] = -1e30f;
            }
        }

        float mx0 = -1e30f, mx1 = -1e30f;
#pragma unroll
        for (int kg = 0; kg < 8; kg++) {
            mx0 = fmaxf(mx0, fmaxf(sc[kg][0], sc[kg][1]));
            mx1 = fmaxf(mx1, fmaxf(sc[kg][2], sc[kg][3]));
        }
        mx0 = fmaxf(mx0, __shfl_xor_sync(0xffffffffu, mx0, 1));
        mx0 = fmaxf(mx0, __shfl_xor_sync(0xffffffffu, mx0, 2));
        mx1 = fmaxf(mx1, __shfl_xor_sync(0xffffffffu, mx1, 1));
        mx1 = fmaxf(mx1, __shfl_xor_sync(0xffffffffu, mx1, 2));

        float nm0 = fmaxf(m0, mx0), nm1 = fmaxf(m1, mx1);
        float rs0 = __expf(m0 - nm0), rs1 = __expf(m1 - nm1);

        float s0 = 0.f, s1 = 0.f;
        uint32_t ph[8][2];
#pragma unroll
        for (int kg = 0; kg < 8; kg++) {
            float p0 = __expf(sc[kg][0] - nm0);
            float p1 = __expf(sc[kg][1] - nm0);
            float p2 = __expf(sc[kg][2] - nm1);
            float p3 = __expf(sc[kg][3] - nm1);
            s0 += p0 + p1;
            s1 += p2 + p3;
            ph[kg][0] = packh2(p0, p1);
            ph[kg][1] = packh2(p2, p3);
        }
        s0 += __shfl_xor_sync(0xffffffffu, s0, 1);
        s0 += __shfl_xor_sync(0xffffffffu, s0, 2);
        s1 += __shfl_xor_sync(0xffffffffu, s1, 1);
        s1 += __shfl_xor_sync(0xffffffffu, s1, 2);

        l0 = l0 * rs0 + s0;
        l1 = l1 * rs1 + s1;
        m0 = nm0; m1 = nm1;

#pragma unroll
        for (int dn = 0; dn < 16; dn++) {
            oacc[dn][0] *= rs0; oacc[dn][1] *= rs0;
            oacc[dn][2] *= rs1; oacc[dn][3] *= rs1;
        }

#pragma unroll
        for (int ck = 0; ck < 4; ck++) {
            uint32_t pa0 = ph[2*ck][0], pa1 = ph[2*ck][1];
            uint32_t pa2 = ph[2*ck+1][0], pa3 = ph[2*ck+1][1];
#pragma unroll
            for (int dp = 0; dp < 8; dp++) {
                uint32_t v0, v1, v2, v3;
                uint32_t vaddr = vs_b +
                    (uint32_t)((((v_rowc + ck * 16) * SQH) + dp * 16 + v_colc) * 2);
                LDMX4T(v0, v1, v2, v3, vaddr);
                mma_f16(oacc[2*dp][0], oacc[2*dp][1], oacc[2*dp][2], oacc[2*dp][3],
                        pa0, pa1, pa2, pa3, v0, v1);
                mma_f16(oacc[2*dp+1][0], oacc[2*dp+1][1], oacc[2*dp+1][2], oacc[2*dp+1][3],
                        pa0, pa1, pa2, pa3, v2, v3);
            }
        }
    }

    // ---- epilogue: normalize + fp16 plain-layout store ----
    float inv0 = 1.f / l0, inv1 = 1.f / l1;
    const int b = bh >> 4, h = bh & (NUM_HEADS - 1);
    size_t rowa = (size_t)(b * SEQ + q0 + qr + g) * HIDDEN;
    size_t rowb = rowa + (size_t)8 * HIDDEN;
#pragma unroll
    for (int dn = 0; dn < 16; dn++) {
        int a = dn & 1;
        int col = h * 128 + (dn >> 1) * 16 + a * 8 + 2 * t;
        *(uint32_t*)&AOh[rowa + col] = packh2(oacc[dn][0] * inv0, oacc[dn][1] * inv0);
        *(uint32_t*)&AOh[rowb + col] = packh2(oacc[dn][2] * inv1, oacc[dn][3] * inv1);
    }
}

// ======================= launch =======================
extern "C" void kernel_launch(void* const* d_in, const int* in_sizes, int n_in,
                              void* d_out, int out_size)
{
    const float* x   = (const float*)d_in[0];
    const float* W_Q = (const float*)d_in[1];
    const float* b_Q = (const float*)d_in[2];
    const float* W_K = (const float*)d_in[3];
    const float* b_K = (const float*)d_in[4];
    const float* W_V = (const float*)d_in[5];
    const float* b_V = (const float*)d_in[6];
    const float* W_O = (const float*)d_in[7];
    const float* b_O = (const float*)d_in[8];
    const float* kw  = (const float*)d_in[9];

    __half *Qh, *Kh, *Vh, *Xh, *AOh, *WTh4;
    cudaGetSymbolAddress((void**)&Qh,   g_Qh);
    cudaGetSymbolAddress((void**)&Kh,   g_Kh);
    cudaGetSymbolAddress((void**)&Vh,   g_Vh);
    cudaGetSymbolAddress((void**)&Xh,   g_Xh);
    cudaGetSymbolAddress((void**)&AOh,  g_AOh);
    cudaGetSymbolAddress((void**)&WTh4, g_WTh4);

    cudaFuncSetAttribute(gemm_qkv,
                         cudaFuncAttributeMaxDynamicSharedMemorySize, GEMM_SMEM_BYTES);
    cudaFuncSetAttribute(gemm_f16,
                         cudaFuncAttributeMaxDynamicSharedMemorySize, GEMM_SMEM_BYTES);
    cudaFuncSetAttribute(swattn_mma,
                         cudaFuncAttributeMaxDynamicSharedMemorySize, ATTN_SMEM_BYTES);

    // 0. rope table + input conversion
    rope_table_kernel<<<SEQ * 64 / 256, 256>>>();
    convert_half_kernel<<<M_ROWS * HIDDEN / (256 * 8), 256>>>(x, Xh);

    // 1. all 4 weight transposes, one launch
    dim3 tg(HIDDEN / 32, HIDDEN / 32, 4);
    dim3 tb(32, 8);
    transpose_convert4_kernel<<<tg, tb>>>(W_Q, W_K, W_V, W_O, WTh4);

    // 2. fused QKV GEMM + RoPE epilogue
    dim3 gq(48, M_ROWS / 128);
    gemm_qkv<<<gq, 256, GEMM_SMEM_BYTES>>>(Xh, WTh4, b_Q, b_K, b_V, kw, Qh, Kh, Vh);

    // 3. attention (128-query tiles)
    dim3 ga(SEQ / 128, BATCH * NUM_HEADS);
    swattn_mma<<<ga, 256, ATTN_SMEM_BYTES>>>(Qh, Kh, Vh, AOh);

    // 4. O projection
    dim3 go(HIDDEN / 128, M_ROWS / 128);
    gemm_f16<<<go, 256, GEMM_SMEM_BYTES>>>(AOh, WTh4 + (size_t)3 * HIDDEN * HIDDEN,
                                           b_O, (float*)d_out);
}